// round 7
// baseline (speedup 1.0000x reference)
#include <cuda_runtime.h>
#include <cuda_bf16.h>
#include <cstdint>

#define BATCH  64
#define SEQ    512
#define INDIM  512
#define HID    1024
#define OUTDIM 512

// ---------------- device scratch ---------------------------------------------
__device__ float          g_xp[(size_t)BATCH * SEQ * HID];     // 128 MB x-projection
__device__ __nv_bfloat16  g_xhi[(size_t)BATCH * SEQ * INDIM];  // X split hi
__device__ __nv_bfloat16  g_xlo[(size_t)BATCH * SEQ * INDIM];  // X split lo
__device__ __nv_bfloat16  g_wihhi[(size_t)HID * INDIM];        // W_ih hi
__device__ __nv_bfloat16  g_wihlo[(size_t)HID * INDIM];        // W_ih lo
__device__ float          g_bias[HID];                         // b_ih + b_hh
__device__ __nv_bfloat16  g_hhi[2 * BATCH * HID];              // hidden hi (ping-pong)
__device__ __nv_bfloat16  g_hlo[2 * BATCH * HID];              // hidden lo
__device__ __nv_bfloat16  g_whi[(size_t)HID * HID];            // W_hh hi
__device__ __nv_bfloat16  g_wlo[(size_t)HID * HID];            // W_hh lo
__device__ unsigned       g_flag[4][32];                       // [bg][jg] step counters

// ---------------- mma / ldmatrix helpers -------------------------------------
__device__ __forceinline__ void ldsm4(uint32_t &r0, uint32_t &r1, uint32_t &r2,
                                      uint32_t &r3, uint32_t addr) {
    asm volatile("ldmatrix.sync.aligned.m8n8.x4.shared.b16 {%0,%1,%2,%3}, [%4];"
                 : "=r"(r0), "=r"(r1), "=r"(r2), "=r"(r3) : "r"(addr));
}
__device__ __forceinline__ void mma16816(float* d, uint32_t a0, uint32_t a1,
                                         uint32_t a2, uint32_t a3,
                                         uint32_t b0, uint32_t b1) {
    asm volatile(
        "mma.sync.aligned.m16n8k16.row.col.f32.bf16.bf16.f32 "
        "{%0,%1,%2,%3},{%4,%5,%6,%7},{%8,%9},{%0,%1,%2,%3};"
        : "+f"(d[0]), "+f"(d[1]), "+f"(d[2]), "+f"(d[3])
        : "r"(a0), "r"(a1), "r"(a2), "r"(a3), "r"(b0), "r"(b1));
}
__device__ __forceinline__ void split_bf16(float v, __nv_bfloat16 &hi, __nv_bfloat16 &lo) {
    hi = __float2bfloat16(v);
    lo = __float2bfloat16(v - __bfloat162float(hi));
}

// ---------------- init: zero hidden buffers + flags --------------------------
__global__ void k_init() {
    int i = blockIdx.x * blockDim.x + threadIdx.x;    // 131072 threads
    if (i < 128) ((unsigned*)g_flag)[i] = 0u;
    if (i < 65536)       ((uint32_t*)g_hhi)[i] = 0u;
    else                 ((uint32_t*)g_hlo)[i - 65536] = 0u;
}

// ---------------- prep: split X, W_hh, W_ih; fold biases ---------------------
__global__ void k_prep(const float* __restrict__ X, const float* __restrict__ Whh,
                       const float* __restrict__ Wih, const float* __restrict__ bih,
                       const float* __restrict__ bhh) {
    int i = blockIdx.x * blockDim.x + threadIdx.x;    // 16777216 threads
    {
        __nv_bfloat16 hi, lo;
        split_bf16(X[i], hi, lo);
        g_xhi[i] = hi; g_xlo[i] = lo;
    }
    if (i < HID * HID) {
        __nv_bfloat16 hi, lo;
        split_bf16(Whh[i], hi, lo);
        g_whi[i] = hi; g_wlo[i] = lo;
    }
    if (i < HID * INDIM) {
        __nv_bfloat16 hi, lo;
        split_bf16(Wih[i], hi, lo);
        g_wihhi[i] = hi; g_wihlo[i] = lo;
    }
    if (i < HID) g_bias[i] = bih[i] + bhh[i];
}

// ---------------- x_proj tensor-core GEMM ------------------------------------
#define XROW     144
#define XA_COMP  (128 * XROW)
#define XA_STAGE (2 * XA_COMP)
#define XB_COMP  (64 * XROW)
#define XB_STAGE (2 * XB_COMP)
#define XS_A     0
#define XS_B     (2 * XA_STAGE)
#define XS_BYTES (XS_B + 2 * XB_STAGE)

__device__ __forceinline__ void xp_stage(uint32_t smb, int s, int kt,
                                         int m0, int n0, int tid) {
    const int kb = kt * 64;
#pragma unroll
    for (int r = 0; r < 8; r++) {
        int q = tid + 256 * r;
        int c = q >> 10, row = (q >> 3) & 127, kg = q & 7;
        const __nv_bfloat16* src =
            (c ? g_xlo : g_xhi) + (size_t)(m0 + row) * INDIM + kb + kg * 8;
        uint32_t dst = smb + XS_A + s * XA_STAGE + c * XA_COMP + row * XROW + kg * 16;
        asm volatile("cp.async.cg.shared.global [%0], [%1], 16;" :: "r"(dst), "l"(src));
    }
#pragma unroll
    for (int r = 0; r < 4; r++) {
        int q = tid + 256 * r;
        int c = q >> 9, row = (q >> 3) & 63, kg = q & 7;
        const __nv_bfloat16* src =
            (c ? g_wihlo : g_wihhi) + (size_t)(n0 + row) * INDIM + kb + kg * 8;
        uint32_t dst = smb + XS_B + s * XB_STAGE + c * XB_COMP + row * XROW + kg * 16;
        asm volatile("cp.async.cg.shared.global [%0], [%1], 16;" :: "r"(dst), "l"(src));
    }
}

__global__ __launch_bounds__(256) void k_xproj()
{
    extern __shared__ char smc[];
    const uint32_t smb = (uint32_t)__cvta_generic_to_shared(smc);

    const int tid  = threadIdx.x;
    const int lane = tid & 31;
    const int w    = tid >> 5;
    const int wm   = (w >> 1) * 32;
    const int wn   = (w & 1) * 32;
    const int m0   = blockIdx.x * 128;
    const int n0   = blockIdx.y * 64;

    float D1[2][4][4], D2[2][4][4];
#pragma unroll
    for (int i = 0; i < 2; i++)
#pragma unroll
        for (int j = 0; j < 4; j++)
#pragma unroll
            for (int r = 0; r < 4; r++) { D1[i][j][r] = 0.f; D2[i][j][r] = 0.f; }

    const uint32_t aoff = (wm + (lane & 15)) * XROW + (lane >> 4) * 16;
    const uint32_t boff = (wn + (lane & 7) + ((lane >> 4) << 3)) * XROW
                        + ((lane >> 3) & 1) * 16;

    xp_stage(smb, 0, 0, m0, n0, tid);
    asm volatile("cp.async.commit_group;");

    for (int kt = 0; kt < INDIM / 64; kt++) {
        const int s = kt & 1;
        if (kt + 1 < INDIM / 64) {
            xp_stage(smb, s ^ 1, kt + 1, m0, n0, tid);
            asm volatile("cp.async.commit_group;");
            asm volatile("cp.async.wait_group 1;");
        } else {
            asm volatile("cp.async.wait_group 0;");
        }
        __syncthreads();

        const uint32_t ah_b = smb + XS_A + s * XA_STAGE + aoff;
        const uint32_t al_b = ah_b + XA_COMP;
        const uint32_t bh_b = smb + XS_B + s * XB_STAGE + boff;
        const uint32_t bl_b = bh_b + XB_COMP;

#pragma unroll
        for (int ks = 0; ks < 4; ks++) {
            const uint32_t ka = ks * 32;
            uint32_t ah[2][4], al[2][4], bh[2][4], bl[2][4];
            ldsm4(ah[0][0], ah[0][1], ah[0][2], ah[0][3], ah_b + ka);
            ldsm4(ah[1][0], ah[1][1], ah[1][2], ah[1][3], ah_b + 16 * XROW + ka);
            ldsm4(al[0][0], al[0][1], al[0][2], al[0][3], al_b + ka);
            ldsm4(al[1][0], al[1][1], al[1][2], al[1][3], al_b + 16 * XROW + ka);
            ldsm4(bh[0][0], bh[0][1], bh[0][2], bh[0][3], bh_b + ka);
            ldsm4(bh[1][0], bh[1][1], bh[1][2], bh[1][3], bh_b + 16 * XROW + ka);
            ldsm4(bl[0][0], bl[0][1], bl[0][2], bl[0][3], bl_b + ka);
            ldsm4(bl[1][0], bl[1][1], bl[1][2], bl[1][3], bl_b + 16 * XROW + ka);
#pragma unroll
            for (int mi = 0; mi < 2; mi++)
#pragma unroll
                for (int tt = 0; tt < 4; tt++) {
                    int h2 = tt >> 1, p = (tt & 1) * 2;
                    mma16816(D1[mi][tt], ah[mi][0], ah[mi][1], ah[mi][2], ah[mi][3],
                             bh[h2][p], bh[h2][p + 1]);
                    mma16816(D2[mi][tt], al[mi][0], al[mi][1], al[mi][2], al[mi][3],
                             bh[h2][p], bh[h2][p + 1]);
                    mma16816(D2[mi][tt], ah[mi][0], ah[mi][1], ah[mi][2], ah[mi][3],
                             bl[h2][p], bl[h2][p + 1]);
                }
        }
        __syncthreads();
    }

    const int rbase = lane >> 2;
    const int cbase = 2 * (lane & 3);
#pragma unroll
    for (int mi = 0; mi < 2; mi++)
#pragma unroll
        for (int tt = 0; tt < 4; tt++) {
            int gm = m0 + wm + mi * 16 + rbase;
            int gn = n0 + wn + tt * 8 + cbase;
            float2 b2 = *(const float2*)&g_bias[gn];
            float2 v;
            v.x = D1[mi][tt][0] + D2[mi][tt][0] + b2.x;
            v.y = D1[mi][tt][1] + D2[mi][tt][1] + b2.y;
            *(float2*)(g_xp + (size_t)gm * HID + gn) = v;
            v.x = D1[mi][tt][2] + D2[mi][tt][2] + b2.x;
            v.y = D1[mi][tt][3] + D2[mi][tt][3] + b2.y;
            *(float2*)(g_xp + (size_t)(gm + 8) * HID + gn) = v;
        }
}

// ---------------- recurrence: persistent tensor-core kernel ------------------
// 128 CTAs x 256 threads; CTA tile 16b x 32j; 4 independent 32-CTA bg chains.
// Warps 0-3 own k<512 (produced by jg 0-15), warps 4-7 own k>=512 (jg 16-31):
// each half polls its own 16 per-CTA flags, stages its own chunk, and syncs
// via a named barrier — no full-CTA sync until the k-reduction.
#define R_CTAS    128
#define R_THREADS 256

#define SM_WHI   0                       // [32][1032] bf16 (row 2064 B)
#define SM_WLO   66048
#define SM_HBUF  132096                  // 2 chunks x 2 comps x [16][520] bf16
#define HB_CHUNK 33280
#define HB_COMP  16640
#define HB_ROW   1040
#define SM_RED   198656                  // [8][528] f32
#define RED_ROW  528
#define SM_BYTES 215552

__global__ __launch_bounds__(R_THREADS, 1) void k_recur()
{
    extern __shared__ char smc[];
    const uint32_t smb = (uint32_t)__cvta_generic_to_shared(smc);
    float* redf = (float*)(smc + SM_RED);

    const int tid  = threadIdx.x;
    const int lane = tid & 31;
    const int w    = tid >> 5;
    const int half = w >> 2;            // 0: k<512, 1: k>=512
    const int kw   = w & 3;             // k sub-slot within half
    const int jg   = blockIdx.x & 31;
    const int bgi  = blockIdx.x >> 5;
    const int cta_j0 = jg * 32;
    const int cta_b0 = bgi * 16;

    // ---- load W slice (32 j x 1024 k, hi+lo) into padded smem ----
#pragma unroll 8
    for (int it = 0; it < 32; it++) {
        int q = tid + R_THREADS * it;
        int comp = q >> 12, row = (q >> 7) & 31, g = q & 127;
        const __nv_bfloat16* src =
            (comp ? g_wlo : g_whi) + (size_t)(cta_j0 + row) * HID + g * 8;
        *(uint4*)(smc + (comp ? SM_WLO : SM_WHI) + row * 2064 + g * 16) =
            *(const uint4*)src;
    }
    __syncthreads();

    uint32_t b_base[2][2];
#pragma unroll
    for (int comp = 0; comp < 2; comp++)
#pragma unroll
        for (int hn = 0; hn < 2; hn++)
            b_base[comp][hn] = smb + (comp ? SM_WLO : SM_WHI)
                + (hn * 16 + (lane >> 4) * 8 + (lane & 7)) * 2064
                + ((lane >> 3) & 1) * 16;

    // warp k-range: [half*512 + kw*128, +128) elems
    const uint32_t kwb = (uint32_t)kw * 256;      // byte offset within chunk

    // ---- hoist all W fragments into registers (8 ktiles x 2 comps x 2 n-halves)
    uint32_t wf[8][2][2][4];
#pragma unroll
    for (int ks = 0; ks < 8; ks++)
#pragma unroll
        for (int comp = 0; comp < 2; comp++)
#pragma unroll
            for (int hn = 0; hn < 2; hn++)
                ldsm4(wf[ks][comp][hn][0], wf[ks][comp][hn][1],
                      wf[ks][comp][hn][2], wf[ks][comp][hn][3],
                      b_base[comp][hn] + half * 1024 + kwb + ks * 32);

    // A-fragment ldmatrix bases (chunk baked in via half)
    uint32_t a_base[2];
#pragma unroll
    for (int comp = 0; comp < 2; comp++)
        a_base[comp] = smb + SM_HBUF + half * HB_CHUNK + comp * HB_COMP
                     + (lane & 15) * HB_ROW + (lane >> 4) * 16;

    const unsigned* my_flags = &g_flag[bgi][half * 16];
    unsigned* my_flag_out = &g_flag[bgi][jg];

    const int o0 = tid * 2;
    const int bl = o0 >> 5, jl = o0 & 31;

    for (int t = 0; t < SEQ; t++) {
        const __nv_bfloat16* hch = g_hhi + (t & 1) * (BATCH * HID) + cta_b0 * HID;
        const __nv_bfloat16* hcl = g_hlo + (t & 1) * (BATCH * HID) + cta_b0 * HID;
        __nv_bfloat16* hnh = g_hhi + ((t + 1) & 1) * (BATCH * HID);
        __nv_bfloat16* hnl = g_hlo + ((t + 1) & 1) * (BATCH * HID);

        float2 xp = __ldg((const float2*)
            (g_xp + ((size_t)(cta_b0 + bl) * SEQ + t) * HID + cta_j0 + jl));

        // ---- per-half producer wait: 16 per-CTA flags, lane-parallel ----
        if (t) {
            const unsigned tgt = (unsigned)t;
            const unsigned* fp = my_flags + (lane & 15);
            unsigned v;
            do {
                asm volatile("ld.acquire.gpu.global.u32 %0, [%1];"
                             : "=r"(v) : "l"(fp));
            } while (__any_sync(0xffffffffu, v < tgt));
        }

        // ---- stage this warp's quarter of its chunk (512 x 16B granules) ----
#pragma unroll
        for (int r = 0; r < 16; r++) {
            int g    = kw * 512 + lane + 32 * r;
            int comp = g >> 10, row = (g >> 6) & 15, col = g & 63;
            const __nv_bfloat16* src =
                (comp ? hcl : hch) + row * HID + half * 512 + col * 8;
            uint32_t dst = smb + SM_HBUF + half * HB_CHUNK + comp * HB_COMP
                         + row * HB_ROW + col * 16;
            asm volatile("cp.async.cg.shared.global [%0], [%1], 16;"
                         :: "r"(dst), "l"(src));
        }
        asm volatile("cp.async.commit_group;");
        asm volatile("cp.async.wait_group 0;");
        // join the 4 warps of this half (they co-staged this chunk)
        asm volatile("bar.sync %0, %1;" :: "r"(1 + half), "r"(128) : "memory");

        float D1[4][4], D2[4][4];
#pragma unroll
        for (int i = 0; i < 4; i++)
#pragma unroll
            for (int j = 0; j < 4; j++) { D1[i][j] = 0.f; D2[i][j] = 0.f; }

#pragma unroll
        for (int ks = 0; ks < 8; ks++) {
            const uint32_t ka = kwb + ks * 32;
            uint32_t ah[4], al[4];
            ldsm4(ah[0], ah[1], ah[2], ah[3], a_base[0] + ka);
            ldsm4(al[0], al[1], al[2], al[3], a_base[1] + ka);
#pragma unroll
            for (int tt = 0; tt < 4; tt++) {
                int h2 = tt >> 1, p = (tt & 1) * 2;
                mma16816(D1[tt], ah[0], ah[1], ah[2], ah[3],
                         wf[ks][0][h2][p], wf[ks][0][h2][p + 1]);
            }
#pragma unroll
            for (int tt = 0; tt < 4; tt++) {
                int h2 = tt >> 1, p = (tt & 1) * 2;
                mma16816(D2[tt], al[0], al[1], al[2], al[3],
                         wf[ks][0][h2][p], wf[ks][0][h2][p + 1]);
            }
#pragma unroll
            for (int tt = 0; tt < 4; tt++) {
                int h2 = tt >> 1, p = (tt & 1) * 2;
                mma16816(D2[tt], ah[0], ah[1], ah[2], ah[3],
                         wf[ks][1][h2][p], wf[ks][1][h2][p + 1]);
            }
        }

        // ---- cross-warp k reduction via smem ----
#pragma unroll
        for (int tt = 0; tt < 4; tt++)
#pragma unroll
            for (int r = 0; r < 4; r++) {
                int b = (lane >> 2) + ((r >= 2) ? 8 : 0);
                int j = tt * 8 + 2 * (lane & 3) + (r & 1);
                redf[w * RED_ROW + b * 33 + j] = D1[tt][r] + D2[tt][r];
            }
        __syncthreads();

        float v0 = 0.f, v1 = 0.f;
#pragma unroll
        for (int ww = 0; ww < 8; ww++) {
            v0 += redf[ww * RED_ROW + bl * 33 + jl];
            v1 += redf[ww * RED_ROW + bl * 33 + jl + 1];
        }
        v0 = tanhf(v0 + xp.x);
        v1 = tanhf(v1 + xp.y);

        __nv_bfloat16 h0, l0, h1, l1;
        split_bf16(v0, h0, l0);
        split_bf16(v1, h1, l1);
        size_t oidx = (size_t)(cta_b0 + bl) * HID + cta_j0 + jl;
        __nv_bfloat162 ph; ph.x = h0; ph.y = h1;
        __nv_bfloat162 pl; pl.x = l0; pl.y = l1;
        *(__nv_bfloat162*)(hnh + oidx) = ph;
        *(__nv_bfloat162*)(hnl + oidx) = pl;

        __syncthreads();
        if (tid == 0)
            asm volatile("st.release.gpu.global.u32 [%0], %1;"
                         :: "l"(my_flag_out), "r"((unsigned)(t + 1)) : "memory");
    }
}

// ---------------- output projection ------------------------------------------
__global__ __launch_bounds__(256) void k_out(
    const float* __restrict__ Who, const float* __restrict__ bho,
    float* __restrict__ out)
{
    const int lane = threadIdx.x & 31;
    const int gw   = blockIdx.x * 8 + (threadIdx.x >> 5);
    const int o0   = (gw >> 3) * 2;
    const int b0   = (gw & 7) * 8;

    const float4* W0 = (const float4*)(Who + (size_t)o0 * HID);
    const float4* W1 = (const float4*)(Who + (size_t)(o0 + 1) * HID);
    float4 wr0[8], wr1[8];
#pragma unroll
    for (int i = 0; i < 8; i++) {
        wr0[i] = W0[i * 32 + lane];
        wr1[i] = W1[i * 32 + lane];
    }
    float bias0 = __ldg(&bho[o0]), bias1 = __ldg(&bho[o0 + 1]);

#pragma unroll
    for (int b = 0; b < 8; b++) {
        const __nv_bfloat16* hh = g_hhi + (size_t)(b0 + b) * HID;  // final h in buf 0
        const __nv_bfloat16* hl = g_hlo + (size_t)(b0 + b) * HID;
        float a0 = 0.f, a1 = 0.f;
#pragma unroll
        for (int i = 0; i < 8; i++) {
            int k0 = lane * 4 + i * 128;
            __nv_bfloat162 ph0 = *(const __nv_bfloat162*)(hh + k0);
            __nv_bfloat162 ph1 = *(const __nv_bfloat162*)(hh + k0 + 2);
            __nv_bfloat162 pl0 = *(const __nv_bfloat162*)(hl + k0);
            __nv_bfloat162 pl1 = *(const __nv_bfloat162*)(hl + k0 + 2);
            float2 f0 = __bfloat1622float2(ph0), g0 = __bfloat1622float2(pl0);
            float2 f1 = __bfloat1622float2(ph1), g1 = __bfloat1622float2(pl1);
            float hx = f0.x + g0.x, hy = f0.y + g0.y;
            float hz = f1.x + g1.x, hw = f1.y + g1.y;
            a0 += hx * wr0[i].x + hy * wr0[i].y + hz * wr0[i].z + hw * wr0[i].w;
            a1 += hx * wr1[i].x + hy * wr1[i].y + hz * wr1[i].z + hw * wr1[i].w;
        }
#pragma unroll
        for (int off = 16; off; off >>= 1) {
            a0 += __shfl_xor_sync(0xffffffffu, a0, off);
            a1 += __shfl_xor_sync(0xffffffffu, a1, off);
        }
        if (lane == 0) {
            out[(size_t)(b0 + b) * OUTDIM + o0]     = a0 + bias0;
            out[(size_t)(b0 + b) * OUTDIM + o0 + 1] = a1 + bias1;
        }
    }
}

// ---------------- launch ------------------------------------------------------
extern "C" void kernel_launch(void* const* d_in, const int* in_sizes, int n_in,
                              void* d_out, int out_size)
{
    (void)in_sizes; (void)n_in; (void)out_size;
    const float* X   = (const float*)d_in[0];
    const float* Wih = (const float*)d_in[1];
    const float* bih = (const float*)d_in[2];
    const float* Whh = (const float*)d_in[3];
    const float* bhh = (const float*)d_in[4];
    const float* Who = (const float*)d_in[5];
    const float* bho = (const float*)d_in[6];
    float* out = (float*)d_out;

    cudaFuncSetAttribute(k_xproj, cudaFuncAttributeMaxDynamicSharedMemorySize,
                         XS_BYTES);
    cudaFuncSetAttribute(k_recur, cudaFuncAttributeMaxDynamicSharedMemorySize,
                         SM_BYTES);

    k_init<<<512, 256>>>();
    k_prep<<<65536, 256>>>(X, Whh, Wih, bih, bhh);
    dim3 xg(BATCH * SEQ / 128, HID / 64);
    k_xproj<<<xg, 256, XS_BYTES>>>();
    k_recur<<<R_CTAS, R_THREADS, SM_BYTES>>>();
    k_out<<<256, 256>>>(Who, bho, out);
}

// round 8
// speedup vs baseline: 1.8793x; 1.8793x over previous
#include <cuda_runtime.h>
#include <cuda_bf16.h>
#include <cstdint>

#define BATCH  64
#define SEQ    512
#define INDIM  512
#define HID    1024
#define OUTDIM 512

// ---------------- device scratch ---------------------------------------------
__device__ float          g_xp[(size_t)BATCH * SEQ * HID];     // 128 MB x-projection
__device__ __nv_bfloat16  g_xhi[(size_t)BATCH * SEQ * INDIM];  // X split hi
__device__ __nv_bfloat16  g_xlo[(size_t)BATCH * SEQ * INDIM];  // X split lo
__device__ __nv_bfloat16  g_wihhi[(size_t)HID * INDIM];        // W_ih hi
__device__ __nv_bfloat16  g_wihlo[(size_t)HID * INDIM];        // W_ih lo
__device__ float          g_bias[HID];                         // b_ih + b_hh
__device__ __nv_bfloat16  g_hhi[2 * BATCH * HID];              // hidden hi (ping-pong)
__device__ __nv_bfloat16  g_hlo[2 * BATCH * HID];              // hidden lo
__device__ __nv_bfloat16  g_whi[(size_t)HID * HID];            // W_hh hi
__device__ __nv_bfloat16  g_wlo[(size_t)HID * HID];            // W_hh lo
__device__ unsigned       g_flag[4][32];                       // [bg][jg] step counters

// ---------------- mma / ldmatrix helpers -------------------------------------
__device__ __forceinline__ void ldsm4(uint32_t &r0, uint32_t &r1, uint32_t &r2,
                                      uint32_t &r3, uint32_t addr) {
    asm volatile("ldmatrix.sync.aligned.m8n8.x4.shared.b16 {%0,%1,%2,%3}, [%4];"
                 : "=r"(r0), "=r"(r1), "=r"(r2), "=r"(r3) : "r"(addr));
}
__device__ __forceinline__ void mma16816(float* d, uint32_t a0, uint32_t a1,
                                         uint32_t a2, uint32_t a3,
                                         uint32_t b0, uint32_t b1) {
    asm volatile(
        "mma.sync.aligned.m16n8k16.row.col.f32.bf16.bf16.f32 "
        "{%0,%1,%2,%3},{%4,%5,%6,%7},{%8,%9},{%0,%1,%2,%3};"
        : "+f"(d[0]), "+f"(d[1]), "+f"(d[2]), "+f"(d[3])
        : "r"(a0), "r"(a1), "r"(a2), "r"(a3), "r"(b0), "r"(b1));
}
__device__ __forceinline__ void split_bf16(float v, __nv_bfloat16 &hi, __nv_bfloat16 &lo) {
    hi = __float2bfloat16(v);
    lo = __float2bfloat16(v - __bfloat162float(hi));
}

// ---------------- init: zero hidden buffers + flags --------------------------
__global__ void k_init() {
    int i = blockIdx.x * blockDim.x + threadIdx.x;    // 131072 threads
    if (i < 128) ((unsigned*)g_flag)[i] = 0u;
    if (i < 65536)       ((uint32_t*)g_hhi)[i] = 0u;
    else                 ((uint32_t*)g_hlo)[i - 65536] = 0u;
}

// ---------------- prep: split X, W_hh, W_ih; fold biases ---------------------
__global__ void k_prep(const float* __restrict__ X, const float* __restrict__ Whh,
                       const float* __restrict__ Wih, const float* __restrict__ bih,
                       const float* __restrict__ bhh) {
    int i = blockIdx.x * blockDim.x + threadIdx.x;    // 16777216 threads
    {
        __nv_bfloat16 hi, lo;
        split_bf16(X[i], hi, lo);
        g_xhi[i] = hi; g_xlo[i] = lo;
    }
    if (i < HID * HID) {
        __nv_bfloat16 hi, lo;
        split_bf16(Whh[i], hi, lo);
        g_whi[i] = hi; g_wlo[i] = lo;
    }
    if (i < HID * INDIM) {
        __nv_bfloat16 hi, lo;
        split_bf16(Wih[i], hi, lo);
        g_wihhi[i] = hi; g_wihlo[i] = lo;
    }
    if (i < HID) g_bias[i] = bih[i] + bhh[i];
}

// ---------------- x_proj tensor-core GEMM ------------------------------------
#define XROW     144
#define XA_COMP  (128 * XROW)
#define XA_STAGE (2 * XA_COMP)
#define XB_COMP  (64 * XROW)
#define XB_STAGE (2 * XB_COMP)
#define XS_A     0
#define XS_B     (2 * XA_STAGE)
#define XS_BYTES (XS_B + 2 * XB_STAGE)

__device__ __forceinline__ void xp_stage(uint32_t smb, int s, int kt,
                                         int m0, int n0, int tid) {
    const int kb = kt * 64;
#pragma unroll
    for (int r = 0; r < 8; r++) {
        int q = tid + 256 * r;
        int c = q >> 10, row = (q >> 3) & 127, kg = q & 7;
        const __nv_bfloat16* src =
            (c ? g_xlo : g_xhi) + (size_t)(m0 + row) * INDIM + kb + kg * 8;
        uint32_t dst = smb + XS_A + s * XA_STAGE + c * XA_COMP + row * XROW + kg * 16;
        asm volatile("cp.async.cg.shared.global [%0], [%1], 16;" :: "r"(dst), "l"(src));
    }
#pragma unroll
    for (int r = 0; r < 4; r++) {
        int q = tid + 256 * r;
        int c = q >> 9, row = (q >> 3) & 63, kg = q & 7;
        const __nv_bfloat16* src =
            (c ? g_wihlo : g_wihhi) + (size_t)(n0 + row) * INDIM + kb + kg * 8;
        uint32_t dst = smb + XS_B + s * XB_STAGE + c * XB_COMP + row * XROW + kg * 16;
        asm volatile("cp.async.cg.shared.global [%0], [%1], 16;" :: "r"(dst), "l"(src));
    }
}

__global__ __launch_bounds__(256) void k_xproj()
{
    extern __shared__ char smc[];
    const uint32_t smb = (uint32_t)__cvta_generic_to_shared(smc);

    const int tid  = threadIdx.x;
    const int lane = tid & 31;
    const int w    = tid >> 5;
    const int wm   = (w >> 1) * 32;
    const int wn   = (w & 1) * 32;
    const int m0   = blockIdx.x * 128;
    const int n0   = blockIdx.y * 64;

    float D1[2][4][4], D2[2][4][4];
#pragma unroll
    for (int i = 0; i < 2; i++)
#pragma unroll
        for (int j = 0; j < 4; j++)
#pragma unroll
            for (int r = 0; r < 4; r++) { D1[i][j][r] = 0.f; D2[i][j][r] = 0.f; }

    const uint32_t aoff = (wm + (lane & 15)) * XROW + (lane >> 4) * 16;
    const uint32_t boff = (wn + (lane & 7) + ((lane >> 4) << 3)) * XROW
                        + ((lane >> 3) & 1) * 16;

    xp_stage(smb, 0, 0, m0, n0, tid);
    asm volatile("cp.async.commit_group;");

    for (int kt = 0; kt < INDIM / 64; kt++) {
        const int s = kt & 1;
        if (kt + 1 < INDIM / 64) {
            xp_stage(smb, s ^ 1, kt + 1, m0, n0, tid);
            asm volatile("cp.async.commit_group;");
            asm volatile("cp.async.wait_group 1;");
        } else {
            asm volatile("cp.async.wait_group 0;");
        }
        __syncthreads();

        const uint32_t ah_b = smb + XS_A + s * XA_STAGE + aoff;
        const uint32_t al_b = ah_b + XA_COMP;
        const uint32_t bh_b = smb + XS_B + s * XB_STAGE + boff;
        const uint32_t bl_b = bh_b + XB_COMP;

#pragma unroll
        for (int ks = 0; ks < 4; ks++) {
            const uint32_t ka = ks * 32;
            uint32_t ah[2][4], al[2][4], bh[2][4], bl[2][4];
            ldsm4(ah[0][0], ah[0][1], ah[0][2], ah[0][3], ah_b + ka);
            ldsm4(ah[1][0], ah[1][1], ah[1][2], ah[1][3], ah_b + 16 * XROW + ka);
            ldsm4(al[0][0], al[0][1], al[0][2], al[0][3], al_b + ka);
            ldsm4(al[1][0], al[1][1], al[1][2], al[1][3], al_b + 16 * XROW + ka);
            ldsm4(bh[0][0], bh[0][1], bh[0][2], bh[0][3], bh_b + ka);
            ldsm4(bh[1][0], bh[1][1], bh[1][2], bh[1][3], bh_b + 16 * XROW + ka);
            ldsm4(bl[0][0], bl[0][1], bl[0][2], bl[0][3], bl_b + ka);
            ldsm4(bl[1][0], bl[1][1], bl[1][2], bl[1][3], bl_b + 16 * XROW + ka);
#pragma unroll
            for (int mi = 0; mi < 2; mi++)
#pragma unroll
                for (int tt = 0; tt < 4; tt++) {
                    int h2 = tt >> 1, p = (tt & 1) * 2;
                    mma16816(D1[mi][tt], ah[mi][0], ah[mi][1], ah[mi][2], ah[mi][3],
                             bh[h2][p], bh[h2][p + 1]);
                    mma16816(D2[mi][tt], al[mi][0], al[mi][1], al[mi][2], al[mi][3],
                             bh[h2][p], bh[h2][p + 1]);
                    mma16816(D2[mi][tt], ah[mi][0], ah[mi][1], ah[mi][2], ah[mi][3],
                             bl[h2][p], bl[h2][p + 1]);
                }
        }
        __syncthreads();
    }

    const int rbase = lane >> 2;
    const int cbase = 2 * (lane & 3);
#pragma unroll
    for (int mi = 0; mi < 2; mi++)
#pragma unroll
        for (int tt = 0; tt < 4; tt++) {
            int gm = m0 + wm + mi * 16 + rbase;
            int gn = n0 + wn + tt * 8 + cbase;
            float2 b2 = *(const float2*)&g_bias[gn];
            float2 v;
            v.x = D1[mi][tt][0] + D2[mi][tt][0] + b2.x;
            v.y = D1[mi][tt][1] + D2[mi][tt][1] + b2.y;
            *(float2*)(g_xp + (size_t)gm * HID + gn) = v;
            v.x = D1[mi][tt][2] + D2[mi][tt][2] + b2.x;
            v.y = D1[mi][tt][3] + D2[mi][tt][3] + b2.y;
            *(float2*)(g_xp + (size_t)(gm + 8) * HID + gn) = v;
        }
}

// ---------------- recurrence: persistent tensor-core kernel ------------------
// 128 CTAs x 256 threads; CTA tile 16b x 32j; 4 independent 32-CTA bg chains.
// Per-CTA release-store flags (no atomic serialization); ONLY warp 0 polls
// (lane-parallel over the 32 peer flags), everyone else parks at syncthreads.
// W_hh fragments hoisted to registers.
#define R_CTAS    128
#define R_THREADS 256

#define SM_WHI   0                       // [32][1032] bf16 (row 2064 B)
#define SM_WLO   66048
#define SM_HBUF  132096                  // 2 chunks x 2 comps x [16][520] bf16
#define HB_CHUNK 33280
#define HB_COMP  16640
#define HB_ROW   1040
#define SM_RED   198656                  // [8][528] f32
#define RED_ROW  528
#define SM_BYTES 215552

__device__ __forceinline__ void stage_chunk(uint32_t dst_base,
                                            const __nv_bfloat16* ghi,
                                            const __nv_bfloat16* glo, int tid) {
#pragma unroll
    for (int r = 0; r < 8; r++) {
        int q    = tid + R_THREADS * r;
        int comp = q >> 10, rr = (q >> 6) & 15, g = q & 63;
        const __nv_bfloat16* src = (comp ? glo : ghi) + rr * HID + g * 8;
        uint32_t dst = dst_base + comp * HB_COMP + rr * HB_ROW + g * 16;
        asm volatile("cp.async.cg.shared.global [%0], [%1], 16;"
                     :: "r"(dst), "l"(src));
    }
}

__global__ __launch_bounds__(R_THREADS, 1) void k_recur()
{
    extern __shared__ char smc[];
    const uint32_t smb = (uint32_t)__cvta_generic_to_shared(smc);
    float* redf = (float*)(smc + SM_RED);

    const int tid  = threadIdx.x;
    const int lane = tid & 31;
    const int w    = tid >> 5;
    const int jg   = blockIdx.x & 31;
    const int bgi  = blockIdx.x >> 5;
    const int cta_j0 = jg * 32;
    const int cta_b0 = bgi * 16;

    unsigned* my_flag_out = &g_flag[bgi][jg];
    const unsigned* my_flags = &g_flag[bgi][0];

    // ---- load W slice (32 j x 1024 k, hi+lo) into padded smem ----
#pragma unroll 8
    for (int it = 0; it < 32; it++) {
        int q = tid + R_THREADS * it;
        int comp = q >> 12, row = (q >> 7) & 31, g = q & 127;
        const __nv_bfloat16* src =
            (comp ? g_wlo : g_whi) + (size_t)(cta_j0 + row) * HID + g * 8;
        *(uint4*)(smc + (comp ? SM_WLO : SM_WHI) + row * 2064 + g * 16) =
            *(const uint4*)src;
    }
    __syncthreads();

    uint32_t a_base[2];
#pragma unroll
    for (int comp = 0; comp < 2; comp++)
        a_base[comp] = smb + SM_HBUF + comp * HB_COMP
                     + (lane & 15) * HB_ROW + (lane >> 4) * 16;
    uint32_t b_base[2][2];
#pragma unroll
    for (int comp = 0; comp < 2; comp++)
#pragma unroll
        for (int half = 0; half < 2; half++)
            b_base[comp][half] = smb + (comp ? SM_WLO : SM_WHI)
                + (half * 16 + (lane >> 4) * 8 + (lane & 7)) * 2064
                + ((lane >> 3) & 1) * 16;

    const int koffw = w * 128;

    // ---- hoist all W fragments into registers (resident for 512 steps) ----
    uint32_t wf[2][4][2][2][4];    // [chunk][ks][comp][half][reg]
#pragma unroll
    for (int c = 0; c < 2; c++)
#pragma unroll
        for (int ks = 0; ks < 4; ks++)
#pragma unroll
            for (int comp = 0; comp < 2; comp++)
#pragma unroll
                for (int half = 0; half < 2; half++)
                    ldsm4(wf[c][ks][comp][half][0], wf[c][ks][comp][half][1],
                          wf[c][ks][comp][half][2], wf[c][ks][comp][half][3],
                          b_base[comp][half] + c * 1024 + koffw + ks * 32);

    const int o0 = tid * 2;
    const int bl = o0 >> 5, jl = o0 & 31;

    for (int t = 0; t < SEQ; t++) {
        const __nv_bfloat16* hch = g_hhi + (t & 1) * (BATCH * HID) + cta_b0 * HID;
        const __nv_bfloat16* hcl = g_hlo + (t & 1) * (BATCH * HID) + cta_b0 * HID;
        __nv_bfloat16* hnh = g_hhi + ((t + 1) & 1) * (BATCH * HID);
        __nv_bfloat16* hnl = g_hlo + ((t + 1) & 1) * (BATCH * HID);

        // wait for all 32 peer CTAs of this bg chain to finish step t-1:
        // warp 0 only, one flag per lane, parallel acquire-poll
        if (t) {
            if (w == 0) {
                const unsigned tgt = (unsigned)t;
                const unsigned* fp = my_flags + lane;
                unsigned v;
                do {
                    asm volatile("ld.acquire.gpu.global.u32 %0, [%1];"
                                 : "=r"(v) : "l"(fp));
                } while (__any_sync(0xffffffffu, v < tgt));
            }
            __syncthreads();
        }

        stage_chunk(smb + SM_HBUF, hch, hcl, tid);
        asm volatile("cp.async.commit_group;");
        stage_chunk(smb + SM_HBUF + HB_CHUNK, hch + 512, hcl + 512, tid);
        asm volatile("cp.async.commit_group;");

        float2 xp = __ldg((const float2*)
            (g_xp + ((size_t)(cta_b0 + bl) * SEQ + t) * HID + cta_j0 + jl));

        float D1[4][4], D2[4][4];
#pragma unroll
        for (int i = 0; i < 4; i++)
#pragma unroll
            for (int j = 0; j < 4; j++) { D1[i][j] = 0.f; D2[i][j] = 0.f; }

        asm volatile("cp.async.wait_group 1;");
        __syncthreads();

#pragma unroll
        for (int c = 0; c < 2; c++) {
            if (c == 1) {
                asm volatile("cp.async.wait_group 0;");
                __syncthreads();
            }
            const uint32_t cb = c * HB_CHUNK;
#pragma unroll
            for (int ks = 0; ks < 4; ks++) {
                const uint32_t ka = koffw + ks * 32;
                uint32_t ah[4], al[4];
                ldsm4(ah[0], ah[1], ah[2], ah[3], a_base[0] + cb + ka);
                ldsm4(al[0], al[1], al[2], al[3], a_base[1] + cb + ka);
#pragma unroll
                for (int tt = 0; tt < 4; tt++) {
                    int h2 = tt >> 1, p = (tt & 1) * 2;
                    mma16816(D1[tt], ah[0], ah[1], ah[2], ah[3],
                             wf[c][ks][0][h2][p], wf[c][ks][0][h2][p + 1]);
                }
#pragma unroll
                for (int tt = 0; tt < 4; tt++) {
                    int h2 = tt >> 1, p = (tt & 1) * 2;
                    mma16816(D2[tt], al[0], al[1], al[2], al[3],
                             wf[c][ks][0][h2][p], wf[c][ks][0][h2][p + 1]);
                }
#pragma unroll
                for (int tt = 0; tt < 4; tt++) {
                    int h2 = tt >> 1, p = (tt & 1) * 2;
                    mma16816(D2[tt], ah[0], ah[1], ah[2], ah[3],
                             wf[c][ks][1][h2][p], wf[c][ks][1][h2][p + 1]);
                }
            }
        }

        // ---- cross-warp k reduction via smem ----
#pragma unroll
        for (int tt = 0; tt < 4; tt++)
#pragma unroll
            for (int r = 0; r < 4; r++) {
                int b = (lane >> 2) + ((r >= 2) ? 8 : 0);
                int j = tt * 8 + 2 * (lane & 3) + (r & 1);
                redf[w * RED_ROW + b * 33 + j] = D1[tt][r] + D2[tt][r];
            }
        __syncthreads();

        float v0 = 0.f, v1 = 0.f;
#pragma unroll
        for (int ww = 0; ww < 8; ww++) {
            v0 += redf[ww * RED_ROW + bl * 33 + jl];
            v1 += redf[ww * RED_ROW + bl * 33 + jl + 1];
        }
        v0 = tanhf(v0 + xp.x);
        v1 = tanhf(v1 + xp.y);

        __nv_bfloat16 h0, l0, h1, l1;
        split_bf16(v0, h0, l0);
        split_bf16(v1, h1, l1);
        size_t oidx = (size_t)(cta_b0 + bl) * HID + cta_j0 + jl;
        __nv_bfloat162 ph; ph.x = h0; ph.y = h1;
        __nv_bfloat162 pl; pl.x = l0; pl.y = l1;
        *(__nv_bfloat162*)(hnh + oidx) = ph;
        *(__nv_bfloat162*)(hnl + oidx) = pl;

        __syncthreads();
        if (tid == 0)
            asm volatile("st.release.gpu.global.u32 [%0], %1;"
                         :: "l"(my_flag_out), "r"((unsigned)(t + 1)) : "memory");
    }
}

// ---------------- output projection ------------------------------------------
__global__ __launch_bounds__(256) void k_out(
    const float* __restrict__ Who, const float* __restrict__ bho,
    float* __restrict__ out)
{
    const int lane = threadIdx.x & 31;
    const int gw   = blockIdx.x * 8 + (threadIdx.x >> 5);
    const int o0   = (gw >> 3) * 2;
    const int b0   = (gw & 7) * 8;

    const float4* W0 = (const float4*)(Who + (size_t)o0 * HID);
    const float4* W1 = (const float4*)(Who + (size_t)(o0 + 1) * HID);
    float4 wr0[8], wr1[8];
#pragma unroll
    for (int i = 0; i < 8; i++) {
        wr0[i] = W0[i * 32 + lane];
        wr1[i] = W1[i * 32 + lane];
    }
    float bias0 = __ldg(&bho[o0]), bias1 = __ldg(&bho[o0 + 1]);

#pragma unroll
    for (int b = 0; b < 8; b++) {
        const __nv_bfloat16* hh = g_hhi + (size_t)(b0 + b) * HID;  // final h in buf 0
        const __nv_bfloat16* hl = g_hlo + (size_t)(b0 + b) * HID;
        float a0 = 0.f, a1 = 0.f;
#pragma unroll
        for (int i = 0; i < 8; i++) {
            int k0 = lane * 4 + i * 128;
            __nv_bfloat162 ph0 = *(const __nv_bfloat162*)(hh + k0);
            __nv_bfloat162 ph1 = *(const __nv_bfloat162*)(hh + k0 + 2);
            __nv_bfloat162 pl0 = *(const __nv_bfloat162*)(hl + k0);
            __nv_bfloat162 pl1 = *(const __nv_bfloat162*)(hl + k0 + 2);
            float2 f0 = __bfloat1622float2(ph0), g0 = __bfloat1622float2(pl0);
            float2 f1 = __bfloat1622float2(ph1), g1 = __bfloat1622float2(pl1);
            float hx = f0.x + g0.x, hy = f0.y + g0.y;
            float hz = f1.x + g1.x, hw = f1.y + g1.y;
            a0 += hx * wr0[i].x + hy * wr0[i].y + hz * wr0[i].z + hw * wr0[i].w;
            a1 += hx * wr1[i].x + hy * wr1[i].y + hz * wr1[i].z + hw * wr1[i].w;
        }
#pragma unroll
        for (int off = 16; off; off >>= 1) {
            a0 += __shfl_xor_sync(0xffffffffu, a0, off);
            a1 += __shfl_xor_sync(0xffffffffu, a1, off);
        }
        if (lane == 0) {
            out[(size_t)(b0 + b) * OUTDIM + o0]     = a0 + bias0;
            out[(size_t)(b0 + b) * OUTDIM + o0 + 1] = a1 + bias1;
        }
    }
}

// ---------------- launch ------------------------------------------------------
extern "C" void kernel_launch(void* const* d_in, const int* in_sizes, int n_in,
                              void* d_out, int out_size)
{
    (void)in_sizes; (void)n_in; (void)out_size;
    const float* X   = (const float*)d_in[0];
    const float* Wih = (const float*)d_in[1];
    const float* bih = (const float*)d_in[2];
    const float* Whh = (const float*)d_in[3];
    const float* bhh = (const float*)d_in[4];
    const float* Who = (const float*)d_in[5];
    const float* bho = (const float*)d_in[6];
    float* out = (float*)d_out;

    cudaFuncSetAttribute(k_xproj, cudaFuncAttributeMaxDynamicSharedMemorySize,
                         XS_BYTES);
    cudaFuncSetAttribute(k_recur, cudaFuncAttributeMaxDynamicSharedMemorySize,
                         SM_BYTES);

    k_init<<<512, 256>>>();
    k_prep<<<65536, 256>>>(X, Whh, Wih, bih, bhh);
    dim3 xg(BATCH * SEQ / 128, HID / 64);
    k_xproj<<<xg, 256, XS_BYTES>>>();
    k_recur<<<R_CTAS, R_THREADS, SM_BYTES>>>();
    k_out<<<256, 256>>>(Who, bho, out);
}

// round 10
// speedup vs baseline: 2.9861x; 1.5889x over previous
#include <cuda_runtime.h>
#include <cuda_bf16.h>
#include <cstdint>

#define BATCH  64
#define SEQ    512
#define INDIM  512
#define HID    1024
#define OUTDIM 512

// ---------------- device scratch ---------------------------------------------
__device__ float          g_xp[(size_t)BATCH * SEQ * HID];     // 128 MB x-projection
__device__ __nv_bfloat16  g_xhi[(size_t)BATCH * SEQ * INDIM];  // X split hi
__device__ __nv_bfloat16  g_xlo[(size_t)BATCH * SEQ * INDIM];  // X split lo
__device__ __nv_bfloat16  g_wihhi[(size_t)HID * INDIM];        // W_ih hi
__device__ __nv_bfloat16  g_wihlo[(size_t)HID * INDIM];        // W_ih lo
__device__ float          g_bias[HID];                         // b_ih + b_hh
__device__ __nv_bfloat16  g_whi[(size_t)HID * HID];            // W_hh hi
__device__ __nv_bfloat16  g_wlo[(size_t)HID * HID];            // W_hh lo
__device__ unsigned       g_sig[4][32];                        // per-bg chain counters

// hidden state: bulk-copy-ready SWIZZLED image
// [par 2][bg 4][comp 2][slab 16][row 16 x 128 B]; within a row, 16B granule g
// stored at ((g ^ (row&7)) << 4)  ->  ldmatrix conflict-free after verbatim copy.
#define IMG_PAR  262144u
#define IMG_BG   65536u
#define IMG_COMP 32768u
__device__ __align__(16) unsigned char g_himg[2 * 4 * IMG_BG];

// ---------------- mma / ldmatrix helpers -------------------------------------
__device__ __forceinline__ void ldsm4(uint32_t &r0, uint32_t &r1, uint32_t &r2,
                                      uint32_t &r3, uint32_t addr) {
    asm volatile("ldmatrix.sync.aligned.m8n8.x4.shared.b16 {%0,%1,%2,%3}, [%4];"
                 : "=r"(r0), "=r"(r1), "=r"(r2), "=r"(r3) : "r"(addr));
}
__device__ __forceinline__ void mma16816(float* d, uint32_t a0, uint32_t a1,
                                         uint32_t a2, uint32_t a3,
                                         uint32_t b0, uint32_t b1) {
    asm volatile(
        "mma.sync.aligned.m16n8k16.row.col.f32.bf16.bf16.f32 "
        "{%0,%1,%2,%3},{%4,%5,%6,%7},{%8,%9},{%0,%1,%2,%3};"
        : "+f"(d[0]), "+f"(d[1]), "+f"(d[2]), "+f"(d[3])
        : "r"(a0), "r"(a1), "r"(a2), "r"(a3), "r"(b0), "r"(b1));
}
__device__ __forceinline__ void split_bf16(float v, __nv_bfloat16 &hi, __nv_bfloat16 &lo) {
    hi = __float2bfloat16(v);
    lo = __float2bfloat16(v - __bfloat162float(hi));
}

// ---------------- init: zero hidden image + signals --------------------------
__global__ void k_init() {
    int i = blockIdx.x * blockDim.x + threadIdx.x;    // 131072 threads
    if (i < 128) ((unsigned*)g_sig)[i] = 0u;
    ((uint32_t*)g_himg)[i] = 0u;                      // 131072 u32 = 512 KB
}

// ---------------- prep: split X, W_hh, W_ih; fold biases ---------------------
__global__ void k_prep(const float* __restrict__ X, const float* __restrict__ Whh,
                       const float* __restrict__ Wih, const float* __restrict__ bih,
                       const float* __restrict__ bhh) {
    int i = blockIdx.x * blockDim.x + threadIdx.x;    // 16777216 threads
    {
        __nv_bfloat16 hi, lo;
        split_bf16(X[i], hi, lo);
        g_xhi[i] = hi; g_xlo[i] = lo;
    }
    if (i < HID * HID) {
        __nv_bfloat16 hi, lo;
        split_bf16(Whh[i], hi, lo);
        g_whi[i] = hi; g_wlo[i] = lo;
    }
    if (i < HID * INDIM) {
        __nv_bfloat16 hi, lo;
        split_bf16(Wih[i], hi, lo);
        g_wihhi[i] = hi; g_wihlo[i] = lo;
    }
    if (i < HID) g_bias[i] = bih[i] + bhh[i];
}

// ---------------- x_proj tensor-core GEMM ------------------------------------
#define XROW     144
#define XA_COMP  (128 * XROW)
#define XA_STAGE (2 * XA_COMP)
#define XB_COMP  (64 * XROW)
#define XB_STAGE (2 * XB_COMP)
#define XS_A     0
#define XS_B     (2 * XA_STAGE)
#define XS_BYTES (XS_B + 2 * XB_STAGE)

__device__ __forceinline__ void xp_stage(uint32_t smb, int s, int kt,
                                         int m0, int n0, int tid) {
    const int kb = kt * 64;
#pragma unroll
    for (int r = 0; r < 8; r++) {
        int q = tid + 256 * r;
        int c = q >> 10, row = (q >> 3) & 127, kg = q & 7;
        const __nv_bfloat16* src =
            (c ? g_xlo : g_xhi) + (size_t)(m0 + row) * INDIM + kb + kg * 8;
        uint32_t dst = smb + XS_A + s * XA_STAGE + c * XA_COMP + row * XROW + kg * 16;
        asm volatile("cp.async.cg.shared.global [%0], [%1], 16;" :: "r"(dst), "l"(src));
    }
#pragma unroll
    for (int r = 0; r < 4; r++) {
        int q = tid + 256 * r;
        int c = q >> 9, row = (q >> 3) & 63, kg = q & 7;
        const __nv_bfloat16* src =
            (c ? g_wihlo : g_wihhi) + (size_t)(n0 + row) * INDIM + kb + kg * 8;
        uint32_t dst = smb + XS_B + s * XB_STAGE + c * XB_COMP + row * XROW + kg * 16;
        asm volatile("cp.async.cg.shared.global [%0], [%1], 16;" :: "r"(dst), "l"(src));
    }
}

__global__ __launch_bounds__(256) void k_xproj()
{
    extern __shared__ char smc[];
    const uint32_t smb = (uint32_t)__cvta_generic_to_shared(smc);

    const int tid  = threadIdx.x;
    const int lane = tid & 31;
    const int w    = tid >> 5;
    const int wm   = (w >> 1) * 32;
    const int wn   = (w & 1) * 32;
    const int m0   = blockIdx.x * 128;
    const int n0   = blockIdx.y * 64;

    float D1[2][4][4], D2[2][4][4];
#pragma unroll
    for (int i = 0; i < 2; i++)
#pragma unroll
        for (int j = 0; j < 4; j++)
#pragma unroll
            for (int r = 0; r < 4; r++) { D1[i][j][r] = 0.f; D2[i][j][r] = 0.f; }

    const uint32_t aoff = (wm + (lane & 15)) * XROW + (lane >> 4) * 16;
    const uint32_t boff = (wn + (lane & 7) + ((lane >> 4) << 3)) * XROW
                        + ((lane >> 3) & 1) * 16;

    xp_stage(smb, 0, 0, m0, n0, tid);
    asm volatile("cp.async.commit_group;");

    for (int kt = 0; kt < INDIM / 64; kt++) {
        const int s = kt & 1;
        if (kt + 1 < INDIM / 64) {
            xp_stage(smb, s ^ 1, kt + 1, m0, n0, tid);
            asm volatile("cp.async.commit_group;");
            asm volatile("cp.async.wait_group 1;");
        } else {
            asm volatile("cp.async.wait_group 0;");
        }
        __syncthreads();

        const uint32_t ah_b = smb + XS_A + s * XA_STAGE + aoff;
        const uint32_t al_b = ah_b + XA_COMP;
        const uint32_t bh_b = smb + XS_B + s * XB_STAGE + boff;
        const uint32_t bl_b = bh_b + XB_COMP;

#pragma unroll
        for (int ks = 0; ks < 4; ks++) {
            const uint32_t ka = ks * 32;
            uint32_t ah[2][4], al[2][4], bh[2][4], bl[2][4];
            ldsm4(ah[0][0], ah[0][1], ah[0][2], ah[0][3], ah_b + ka);
            ldsm4(ah[1][0], ah[1][1], ah[1][2], ah[1][3], ah_b + 16 * XROW + ka);
            ldsm4(al[0][0], al[0][1], al[0][2], al[0][3], al_b + ka);
            ldsm4(al[1][0], al[1][1], al[1][2], al[1][3], al_b + 16 * XROW + ka);
            ldsm4(bh[0][0], bh[0][1], bh[0][2], bh[0][3], bh_b + ka);
            ldsm4(bh[1][0], bh[1][1], bh[1][2], bh[1][3], bh_b + 16 * XROW + ka);
            ldsm4(bl[0][0], bl[0][1], bl[0][2], bl[0][3], bl_b + ka);
            ldsm4(bl[1][0], bl[1][1], bl[1][2], bl[1][3], bl_b + 16 * XROW + ka);
#pragma unroll
            for (int mi = 0; mi < 2; mi++)
#pragma unroll
                for (int tt = 0; tt < 4; tt++) {
                    int h2 = tt >> 1, p = (tt & 1) * 2;
                    mma16816(D1[mi][tt], ah[mi][0], ah[mi][1], ah[mi][2], ah[mi][3],
                             bh[h2][p], bh[h2][p + 1]);
                    mma16816(D2[mi][tt], al[mi][0], al[mi][1], al[mi][2], al[mi][3],
                             bh[h2][p], bh[h2][p + 1]);
                    mma16816(D2[mi][tt], ah[mi][0], ah[mi][1], ah[mi][2], ah[mi][3],
                             bl[h2][p], bl[h2][p + 1]);
                }
        }
        __syncthreads();
    }

    const int rbase = lane >> 2;
    const int cbase = 2 * (lane & 3);
#pragma unroll
    for (int mi = 0; mi < 2; mi++)
#pragma unroll
        for (int tt = 0; tt < 4; tt++) {
            int gm = m0 + wm + mi * 16 + rbase;
            int gn = n0 + wn + tt * 8 + cbase;
            float2 b2 = *(const float2*)&g_bias[gn];
            float2 v;
            v.x = D1[mi][tt][0] + D2[mi][tt][0] + b2.x;
            v.y = D1[mi][tt][1] + D2[mi][tt][1] + b2.y;
            *(float2*)(g_xp + (size_t)gm * HID + gn) = v;
            v.x = D1[mi][tt][2] + D2[mi][tt][2] + b2.x;
            v.y = D1[mi][tt][3] + D2[mi][tt][3] + b2.y;
            *(float2*)(g_xp + (size_t)(gm + 8) * HID + gn) = v;
        }
}

// ---------------- recurrence: persistent tensor-core kernel ------------------
// 128 CTAs x 256 threads; CTA tile 16b x 32j; 4 independent 32-CTA bg chains,
// R5 signaling (red.release counter + tid0 acquire-poll). h exchange: ONE
// 64 KB cp.async.bulk per step from the swizzled global image + mbarrier.
#define R_CTAS    128
#define R_THREADS 256

#define SM_WHI   0                       // [32][1032] bf16 (row 2064 B)
#define SM_WLO   66048
#define SM_HBUF  132096                  // 64 KB swizzled h image slice
#define SM_RED   197632                  // [8][528] f32
#define RED_ROW  528
#define SM_MBAR  214528
#define SM_BYTES 214784

__global__ __launch_bounds__(R_THREADS, 1) void k_recur()
{
    extern __shared__ char smc[];
    const uint32_t smb = (uint32_t)__cvta_generic_to_shared(smc);
    float* redf = (float*)(smc + SM_RED);

    const int tid  = threadIdx.x;
    const int lane = tid & 31;
    const int w    = tid >> 5;
    const int jg   = blockIdx.x & 31;
    const int bgi  = blockIdx.x >> 5;
    const int cta_j0 = jg * 32;
    const int cta_b0 = bgi * 16;

    unsigned* my_sig = &g_sig[bgi][0];

    // ---- load W slice (32 j x 1024 k, hi+lo) into padded smem ----
#pragma unroll 8
    for (int it = 0; it < 32; it++) {
        int q = tid + R_THREADS * it;
        int comp = q >> 12, row = (q >> 7) & 31, g = q & 127;
        const __nv_bfloat16* src =
            (comp ? g_wlo : g_whi) + (size_t)(cta_j0 + row) * HID + g * 8;
        *(uint4*)(smc + (comp ? SM_WLO : SM_WHI) + row * 2064 + g * 16) =
            *(const uint4*)src;
    }
    __syncthreads();

    uint32_t b_base[2][2];
#pragma unroll
    for (int comp = 0; comp < 2; comp++)
#pragma unroll
        for (int half = 0; half < 2; half++)
            b_base[comp][half] = smb + (comp ? SM_WLO : SM_WHI)
                + (half * 16 + (lane >> 4) * 8 + (lane & 7)) * 2064
                + ((lane >> 3) & 1) * 16;

    const int koffw = w * 128;

    // ---- hoist all W fragments into registers (resident for 512 steps) ----
    uint32_t wf[2][4][2][2][4];    // [chunk][ks][comp][half][reg]
#pragma unroll
    for (int c = 0; c < 2; c++)
#pragma unroll
        for (int ks = 0; ks < 4; ks++)
#pragma unroll
            for (int comp = 0; comp < 2; comp++)
#pragma unroll
                for (int half = 0; half < 2; half++)
                    ldsm4(wf[c][ks][comp][half][0], wf[c][ks][comp][half][1],
                          wf[c][ks][comp][half][2], wf[c][ks][comp][half][3],
                          b_base[comp][half] + c * 1024 + koffw + ks * 32);

    // ---- mbarrier init ----
    const uint32_t mbar = smb + SM_MBAR;
    if (tid == 0) {
        asm volatile("mbarrier.init.shared.b64 [%0], %1;"
                     :: "r"(mbar), "r"(1u) : "memory");
        asm volatile("fence.proxy.async;" ::: "memory");
    }
    __syncthreads();

    // ---- A-fragment swizzled address components ----
    const int arow = lane & 15;          // m row
    const int ahi  = lane >> 4;          // k8 half select
    const int axr  = arow & 7;           // swizzle xor
    uint32_t a_comp[2];
#pragma unroll
    for (int comp = 0; comp < 2; comp++)
        a_comp[comp] = smb + SM_HBUF + comp * IMG_COMP + arow * 128;

    const int o0 = tid * 2;
    const int bl = o0 >> 5, jl = o0 & 31;
    // producer store swizzle components (col = cta_j0 + jl, even)
    const int pcol  = cta_j0 + jl;
    const uint32_t pbase = (uint32_t)bgi * IMG_BG
        + (pcol >> 6) * 2048 + bl * 128
        + (((((pcol >> 3) & 7)) ^ (bl & 7)) << 4) + (pcol & 7) * 2;

    for (int t = 0; t < SEQ; t++) {
        const unsigned phase = (unsigned)(t & 1);

        // tid0: wait peers (step t-1 done), then launch the bulk copy
        if (tid == 0) {
            if (t) {
                const unsigned need = 32u * (unsigned)t;
                unsigned v;
                do {
                    asm volatile("ld.acquire.gpu.global.u32 %0, [%1];"
                                 : "=r"(v) : "l"(my_sig));
                } while (v < need);
            }
            asm volatile("fence.proxy.async;" ::: "memory");
            asm volatile("mbarrier.arrive.expect_tx.shared.b64 _, [%0], %1;"
                         :: "r"(mbar), "r"(IMG_BG) : "memory");
            const unsigned char* src =
                g_himg + (t & 1) * IMG_PAR + bgi * IMG_BG;
            asm volatile(
                "cp.async.bulk.shared::cluster.global.mbarrier::complete_tx::bytes"
                " [%0], [%1], %2, [%3];"
                :: "r"(smb + SM_HBUF), "l"(src), "r"(IMG_BG), "r"(mbar)
                : "memory");
        }

        float2 xp = __ldg((const float2*)
            (g_xp + ((size_t)(cta_b0 + bl) * SEQ + t) * HID + cta_j0 + jl));

        float D1[4][4], D2[4][4];
#pragma unroll
        for (int i = 0; i < 4; i++)
#pragma unroll
            for (int j = 0; j < 4; j++) { D1[i][j] = 0.f; D2[i][j] = 0.f; }

        // all threads wait for the 64 KB slice
        {
            uint32_t done;
            asm volatile(
                "{\n\t.reg .pred p;\n\t"
                "mbarrier.try_wait.parity.acquire.cta.shared::cta.b64 p, [%1], %2;\n\t"
                "selp.b32 %0, 1, 0, p;\n\t}"
                : "=r"(done) : "r"(mbar), "r"(phase) : "memory");
            if (!done) {
                asm volatile(
                    "{\n\t.reg .pred P1;\n\t"
                    "W%=:\n\t"
                    "mbarrier.try_wait.parity.acquire.cta.shared::cta.b64 P1, [%0], %1, 0x989680;\n\t"
                    "@P1 bra.uni D%=;\n\t"
                    "bra.uni W%=;\n\t"
                    "D%=:\n\t}"
                    :: "r"(mbar), "r"(phase) : "memory");
            }
        }

#pragma unroll
        for (int c = 0; c < 2; c++) {
            const uint32_t slabt = (uint32_t)(c * 8 + w) * 2048;
#pragma unroll
            for (int ks = 0; ks < 4; ks++) {
                const uint32_t gsw = (uint32_t)(((ks * 2 + ahi) ^ axr) << 4);
                uint32_t ah[4], al[4];
                ldsm4(ah[0], ah[1], ah[2], ah[3], a_comp[0] + slabt + gsw);
                ldsm4(al[0], al[1], al[2], al[3], a_comp[1] + slabt + gsw);
#pragma unroll
                for (int tt = 0; tt < 4; tt++) {
                    int h2 = tt >> 1, p = (tt & 1) * 2;
                    mma16816(D1[tt], ah[0], ah[1], ah[2], ah[3],
                             wf[c][ks][0][h2][p], wf[c][ks][0][h2][p + 1]);
                }
#pragma unroll
                for (int tt = 0; tt < 4; tt++) {
                    int h2 = tt >> 1, p = (tt & 1) * 2;
                    mma16816(D2[tt], al[0], al[1], al[2], al[3],
                             wf[c][ks][0][h2][p], wf[c][ks][0][h2][p + 1]);
                }
#pragma unroll
                for (int tt = 0; tt < 4; tt++) {
                    int h2 = tt >> 1, p = (tt & 1) * 2;
                    mma16816(D2[tt], ah[0], ah[1], ah[2], ah[3],
                             wf[c][ks][1][h2][p], wf[c][ks][1][h2][p + 1]);
                }
            }
        }

        // ---- cross-warp k reduction via smem ----
#pragma unroll
        for (int tt = 0; tt < 4; tt++)
#pragma unroll
            for (int r = 0; r < 4; r++) {
                int b = (lane >> 2) + ((r >= 2) ? 8 : 0);
                int j = tt * 8 + 2 * (lane & 3) + (r & 1);
                redf[w * RED_ROW + b * 33 + j] = D1[tt][r] + D2[tt][r];
            }
        __syncthreads();

        float v0 = 0.f, v1 = 0.f;
#pragma unroll
        for (int ww = 0; ww < 8; ww++) {
            v0 += redf[ww * RED_ROW + bl * 33 + jl];
            v1 += redf[ww * RED_ROW + bl * 33 + jl + 1];
        }
        v0 = tanhf(v0 + xp.x);
        v1 = tanhf(v1 + xp.y);

        __nv_bfloat16 h0, l0, h1, l1;
        split_bf16(v0, h0, l0);
        split_bf16(v1, h1, l1);
        unsigned char* hb = g_himg + ((t + 1) & 1) * IMG_PAR + pbase;
        __nv_bfloat162 ph; ph.x = h0; ph.y = h1;
        __nv_bfloat162 pl; pl.x = l0; pl.y = l1;
        *(__nv_bfloat162*)(hb)            = ph;
        *(__nv_bfloat162*)(hb + IMG_COMP) = pl;

        __syncthreads();
        if (tid == 0)
            asm volatile("red.release.gpu.global.add.u32 [%0], %1;"
                         :: "l"(my_sig), "r"(1u));
    }
}

// ---------------- output projection ------------------------------------------
__global__ __launch_bounds__(256) void k_out(
    const float* __restrict__ Who, const float* __restrict__ bho,
    float* __restrict__ out)
{
    const int lane = threadIdx.x & 31;
    const int gw   = blockIdx.x * 8 + (threadIdx.x >> 5);
    const int o0   = (gw >> 3) * 2;
    const int b0   = (gw & 7) * 8;

    const float4* W0 = (const float4*)(Who + (size_t)o0 * HID);
    const float4* W1 = (const float4*)(Who + (size_t)(o0 + 1) * HID);
    float4 wr0[8], wr1[8];
#pragma unroll
    for (int i = 0; i < 8; i++) {
        wr0[i] = W0[i * 32 + lane];
        wr1[i] = W1[i * 32 + lane];
    }
    float bias0 = __ldg(&bho[o0]), bias1 = __ldg(&bho[o0 + 1]);

    const int slabh = lane >> 4;          // slab parity
    const int gran  = (lane & 15) >> 1;   // granule 0..7
    const int bofs  = (lane & 1) * 8;     // byte offset within 16B granule (8B aligned)

#pragma unroll
    for (int b = 0; b < 8; b++) {
        const int bb = b0 + b;
        const int bg = bb >> 4, r = bb & 15;
        // final h (after step 511) lives in parity 0 of the swizzled image
        const unsigned char* base = g_himg + bg * IMG_BG + r * 128
                                  + ((gran ^ (r & 7)) << 4) + bofs;
        float a0 = 0.f, a1 = 0.f;
#pragma unroll
        for (int i = 0; i < 8; i++) {
            const uint32_t sl = (uint32_t)(i * 2 + slabh) * 2048;
            uint2 uh = *(const uint2*)(base + sl);
            uint2 ul = *(const uint2*)(base + IMG_COMP + sl);
            float2 f0 = __bfloat1622float2(*(__nv_bfloat162*)&uh.x);
            float2 f1 = __bfloat1622float2(*(__nv_bfloat162*)&uh.y);
            float2 g0 = __bfloat1622float2(*(__nv_bfloat162*)&ul.x);
            float2 g1 = __bfloat1622float2(*(__nv_bfloat162*)&ul.y);
            float hx = f0.x + g0.x, hy = f0.y + g0.y;
            float hz = f1.x + g1.x, hw = f1.y + g1.y;
            a0 += hx * wr0[i].x + hy * wr0[i].y + hz * wr0[i].z + hw * wr0[i].w;
            a1 += hx * wr1[i].x + hy * wr1[i].y + hz * wr1[i].z + hw * wr1[i].w;
        }
#pragma unroll
        for (int off = 16; off; off >>= 1) {
            a0 += __shfl_xor_sync(0xffffffffu, a0, off);
            a1 += __shfl_xor_sync(0xffffffffu, a1, off);
        }
        if (lane == 0) {
            out[(size_t)bb * OUTDIM + o0]     = a0 + bias0;
            out[(size_t)bb * OUTDIM + o0 + 1] = a1 + bias1;
        }
    }
}

// ---------------- launch ------------------------------------------------------
extern "C" void kernel_launch(void* const* d_in, const int* in_sizes, int n_in,
                              void* d_out, int out_size)
{
    (void)in_sizes; (void)n_in; (void)out_size;
    const float* X   = (const float*)d_in[0];
    const float* Wih = (const float*)d_in[1];
    const float* bih = (const float*)d_in[2];
    const float* Whh = (const float*)d_in[3];
    const float* bhh = (const float*)d_in[4];
    const float* Who = (const float*)d_in[5];
    const float* bho = (const float*)d_in[6];
    float* out = (float*)d_out;

    cudaFuncSetAttribute(k_xproj, cudaFuncAttributeMaxDynamicSharedMemorySize,
                         XS_BYTES);
    cudaFuncSetAttribute(k_recur, cudaFuncAttributeMaxDynamicSharedMemorySize,
                         SM_BYTES);

    k_init<<<512, 256>>>();
    k_prep<<<65536, 256>>>(X, Whh, Wih, bih, bhh);
    dim3 xg(BATCH * SEQ / 128, HID / 64);
    k_xproj<<<xg, 256, XS_BYTES>>>();
    k_recur<<<R_CTAS, R_THREADS, SM_BYTES>>>();
    k_out<<<256, 256>>>(Who, bho, out);
}

// round 11
// speedup vs baseline: 3.0996x; 1.0380x over previous
#include <cuda_runtime.h>
#include <cuda_bf16.h>
#include <cstdint>

#define BATCH  64
#define SEQ    512
#define INDIM  512
#define HID    1024
#define OUTDIM 512

// ---------------- device scratch ---------------------------------------------
__device__ float          g_xp[(size_t)BATCH * SEQ * HID];     // 128 MB x-projection
__device__ __nv_bfloat16  g_xhi[(size_t)BATCH * SEQ * INDIM];  // X split hi
__device__ __nv_bfloat16  g_xlo[(size_t)BATCH * SEQ * INDIM];  // X split lo
__device__ __nv_bfloat16  g_wihhi[(size_t)HID * INDIM];        // W_ih hi
__device__ __nv_bfloat16  g_wihlo[(size_t)HID * INDIM];        // W_ih lo
__device__ float          g_bias[HID];                         // b_ih + b_hh
__device__ __nv_bfloat16  g_whi[(size_t)HID * HID];            // W_hh hi
__device__ __nv_bfloat16  g_wlo[(size_t)HID * HID];            // W_hh lo
__device__ unsigned       g_sig[4][2][32];                     // [bg][half] counters, padded lines

// hidden state: bulk-copy-ready SWIZZLED image, chunk-major
// [par 2][bg 4][chunk 2][comp 2][slab 8][row 16 x 128 B]; within a row,
// 16B granule g stored at ((g ^ (row&7)) << 4) -> ldmatrix conflict-free.
#define IMG_PAR  262144u
#define IMG_BG   65536u
#define IMG_CHK  32768u
#define IMG_CMP  16384u
__device__ __align__(16) unsigned char g_himg[2 * 4 * IMG_BG];

// ---------------- mma / ldmatrix helpers -------------------------------------
__device__ __forceinline__ void ldsm4(uint32_t &r0, uint32_t &r1, uint32_t &r2,
                                      uint32_t &r3, uint32_t addr) {
    asm volatile("ldmatrix.sync.aligned.m8n8.x4.shared.b16 {%0,%1,%2,%3}, [%4];"
                 : "=r"(r0), "=r"(r1), "=r"(r2), "=r"(r3) : "r"(addr));
}
__device__ __forceinline__ void mma16816(float* d, uint32_t a0, uint32_t a1,
                                         uint32_t a2, uint32_t a3,
                                         uint32_t b0, uint32_t b1) {
    asm volatile(
        "mma.sync.aligned.m16n8k16.row.col.f32.bf16.bf16.f32 "
        "{%0,%1,%2,%3},{%4,%5,%6,%7},{%8,%9},{%0,%1,%2,%3};"
        : "+f"(d[0]), "+f"(d[1]), "+f"(d[2]), "+f"(d[3])
        : "r"(a0), "r"(a1), "r"(a2), "r"(a3), "r"(b0), "r"(b1));
}
__device__ __forceinline__ void split_bf16(float v, __nv_bfloat16 &hi, __nv_bfloat16 &lo) {
    hi = __float2bfloat16(v);
    lo = __float2bfloat16(v - __bfloat162float(hi));
}
__device__ __forceinline__ void mbar_wait(uint32_t mbar, unsigned phase) {
    uint32_t done;
    asm volatile(
        "{\n\t.reg .pred p;\n\t"
        "mbarrier.try_wait.parity.acquire.cta.shared::cta.b64 p, [%1], %2;\n\t"
        "selp.b32 %0, 1, 0, p;\n\t}"
        : "=r"(done) : "r"(mbar), "r"(phase) : "memory");
    if (!done) {
        asm volatile(
            "{\n\t.reg .pred P1;\n\t"
            "W%=:\n\t"
            "mbarrier.try_wait.parity.acquire.cta.shared::cta.b64 P1, [%0], %1, 0x989680;\n\t"
            "@P1 bra.uni D%=;\n\t"
            "bra.uni W%=;\n\t"
            "D%=:\n\t}"
            :: "r"(mbar), "r"(phase) : "memory");
    }
}

// ---------------- init: zero hidden image + signals --------------------------
__global__ void k_init() {
    int i = blockIdx.x * blockDim.x + threadIdx.x;    // 131072 threads
    if (i < 256) ((unsigned*)g_sig)[i] = 0u;
    ((uint32_t*)g_himg)[i] = 0u;                      // 131072 u32 = 512 KB
}

// ---------------- prep: split X, W_hh, W_ih; fold biases ---------------------
__global__ void k_prep(const float* __restrict__ X, const float* __restrict__ Whh,
                       const float* __restrict__ Wih, const float* __restrict__ bih,
                       const float* __restrict__ bhh) {
    int i = blockIdx.x * blockDim.x + threadIdx.x;    // 16777216 threads
    {
        __nv_bfloat16 hi, lo;
        split_bf16(X[i], hi, lo);
        g_xhi[i] = hi; g_xlo[i] = lo;
    }
    if (i < HID * HID) {
        __nv_bfloat16 hi, lo;
        split_bf16(Whh[i], hi, lo);
        g_whi[i] = hi; g_wlo[i] = lo;
    }
    if (i < HID * INDIM) {
        __nv_bfloat16 hi, lo;
        split_bf16(Wih[i], hi, lo);
        g_wihhi[i] = hi; g_wihlo[i] = lo;
    }
    if (i < HID) g_bias[i] = bih[i] + bhh[i];
}

// ---------------- x_proj tensor-core GEMM ------------------------------------
#define XROW     144
#define XA_COMP  (128 * XROW)
#define XA_STAGE (2 * XA_COMP)
#define XB_COMP  (64 * XROW)
#define XB_STAGE (2 * XB_COMP)
#define XS_A     0
#define XS_B     (2 * XA_STAGE)
#define XS_BYTES (XS_B + 2 * XB_STAGE)

__device__ __forceinline__ void xp_stage(uint32_t smb, int s, int kt,
                                         int m0, int n0, int tid) {
    const int kb = kt * 64;
#pragma unroll
    for (int r = 0; r < 8; r++) {
        int q = tid + 256 * r;
        int c = q >> 10, row = (q >> 3) & 127, kg = q & 7;
        const __nv_bfloat16* src =
            (c ? g_xlo : g_xhi) + (size_t)(m0 + row) * INDIM + kb + kg * 8;
        uint32_t dst = smb + XS_A + s * XA_STAGE + c * XA_COMP + row * XROW + kg * 16;
        asm volatile("cp.async.cg.shared.global [%0], [%1], 16;" :: "r"(dst), "l"(src));
    }
#pragma unroll
    for (int r = 0; r < 4; r++) {
        int q = tid + 256 * r;
        int c = q >> 9, row = (q >> 3) & 63, kg = q & 7;
        const __nv_bfloat16* src =
            (c ? g_wihlo : g_wihhi) + (size_t)(n0 + row) * INDIM + kb + kg * 8;
        uint32_t dst = smb + XS_B + s * XB_STAGE + c * XB_COMP + row * XROW + kg * 16;
        asm volatile("cp.async.cg.shared.global [%0], [%1], 16;" :: "r"(dst), "l"(src));
    }
}

__global__ __launch_bounds__(256) void k_xproj()
{
    extern __shared__ char smc[];
    const uint32_t smb = (uint32_t)__cvta_generic_to_shared(smc);

    const int tid  = threadIdx.x;
    const int lane = tid & 31;
    const int w    = tid >> 5;
    const int wm   = (w >> 1) * 32;
    const int wn   = (w & 1) * 32;
    const int m0   = blockIdx.x * 128;
    const int n0   = blockIdx.y * 64;

    float D1[2][4][4], D2[2][4][4];
#pragma unroll
    for (int i = 0; i < 2; i++)
#pragma unroll
        for (int j = 0; j < 4; j++)
#pragma unroll
            for (int r = 0; r < 4; r++) { D1[i][j][r] = 0.f; D2[i][j][r] = 0.f; }

    const uint32_t aoff = (wm + (lane & 15)) * XROW + (lane >> 4) * 16;
    const uint32_t boff = (wn + (lane & 7) + ((lane >> 4) << 3)) * XROW
                        + ((lane >> 3) & 1) * 16;

    xp_stage(smb, 0, 0, m0, n0, tid);
    asm volatile("cp.async.commit_group;");

    for (int kt = 0; kt < INDIM / 64; kt++) {
        const int s = kt & 1;
        if (kt + 1 < INDIM / 64) {
            xp_stage(smb, s ^ 1, kt + 1, m0, n0, tid);
            asm volatile("cp.async.commit_group;");
            asm volatile("cp.async.wait_group 1;");
        } else {
            asm volatile("cp.async.wait_group 0;");
        }
        __syncthreads();

        const uint32_t ah_b = smb + XS_A + s * XA_STAGE + aoff;
        const uint32_t al_b = ah_b + XA_COMP;
        const uint32_t bh_b = smb + XS_B + s * XB_STAGE + boff;
        const uint32_t bl_b = bh_b + XB_COMP;

#pragma unroll
        for (int ks = 0; ks < 4; ks++) {
            const uint32_t ka = ks * 32;
            uint32_t ah[2][4], al[2][4], bh[2][4], bl[2][4];
            ldsm4(ah[0][0], ah[0][1], ah[0][2], ah[0][3], ah_b + ka);
            ldsm4(ah[1][0], ah[1][1], ah[1][2], ah[1][3], ah_b + 16 * XROW + ka);
            ldsm4(al[0][0], al[0][1], al[0][2], al[0][3], al_b + ka);
            ldsm4(al[1][0], al[1][1], al[1][2], al[1][3], al_b + 16 * XROW + ka);
            ldsm4(bh[0][0], bh[0][1], bh[0][2], bh[0][3], bh_b + ka);
            ldsm4(bh[1][0], bh[1][1], bh[1][2], bh[1][3], bh_b + 16 * XROW + ka);
            ldsm4(bl[0][0], bl[0][1], bl[0][2], bl[0][3], bl_b + ka);
            ldsm4(bl[1][0], bl[1][1], bl[1][2], bl[1][3], bl_b + 16 * XROW + ka);
#pragma unroll
            for (int mi = 0; mi < 2; mi++)
#pragma unroll
                for (int tt = 0; tt < 4; tt++) {
                    int h2 = tt >> 1, p = (tt & 1) * 2;
                    mma16816(D1[mi][tt], ah[mi][0], ah[mi][1], ah[mi][2], ah[mi][3],
                             bh[h2][p], bh[h2][p + 1]);
                    mma16816(D2[mi][tt], al[mi][0], al[mi][1], al[mi][2], al[mi][3],
                             bh[h2][p], bh[h2][p + 1]);
                    mma16816(D2[mi][tt], ah[mi][0], ah[mi][1], ah[mi][2], ah[mi][3],
                             bl[h2][p], bl[h2][p + 1]);
                }
        }
        __syncthreads();
    }

    const int rbase = lane >> 2;
    const int cbase = 2 * (lane & 3);
#pragma unroll
    for (int mi = 0; mi < 2; mi++)
#pragma unroll
        for (int tt = 0; tt < 4; tt++) {
            int gm = m0 + wm + mi * 16 + rbase;
            int gn = n0 + wn + tt * 8 + cbase;
            float2 b2 = *(const float2*)&g_bias[gn];
            float2 v;
            v.x = D1[mi][tt][0] + D2[mi][tt][0] + b2.x;
            v.y = D1[mi][tt][1] + D2[mi][tt][1] + b2.y;
            *(float2*)(g_xp + (size_t)gm * HID + gn) = v;
            v.x = D1[mi][tt][2] + D2[mi][tt][2] + b2.x;
            v.y = D1[mi][tt][3] + D2[mi][tt][3] + b2.y;
            *(float2*)(g_xp + (size_t)(gm + 8) * HID + gn) = v;
        }
}

// ---------------- recurrence: persistent tensor-core kernel ------------------
// 128 CTAs x 256 threads; 4 independent 32-CTA bg chains; per-HALF counters:
// tid0 orchestrates chunk0 (k<512, producers jg 0-15), tid32 chunk1 — parallel
// detection + 32KB bulk copies, each into its own mbarrier. Warps pipeline:
// wait mbar0 -> compute c0 -> wait mbar1 -> compute c1 -> reduce.
#define R_CTAS    128
#define R_THREADS 256

#define SM_WHI   0                       // [32][1032] bf16 (row 2064 B)
#define SM_WLO   66048
#define SM_HBUF  132096                  // 64 KB swizzled h image slice
#define SM_RED   197632                  // [8][528] f32
#define RED_ROW  528
#define SM_MBAR  214528                  // 2 mbarriers
#define SM_BYTES 214784

__global__ __launch_bounds__(R_THREADS, 1) void k_recur()
{
    extern __shared__ char smc[];
    const uint32_t smb = (uint32_t)__cvta_generic_to_shared(smc);
    float* redf = (float*)(smc + SM_RED);

    const int tid  = threadIdx.x;
    const int lane = tid & 31;
    const int w    = tid >> 5;
    const int jg   = blockIdx.x & 31;
    const int bgi  = blockIdx.x >> 5;
    const int cta_j0 = jg * 32;
    const int cta_b0 = bgi * 16;

    unsigned* my_sig_out = &g_sig[bgi][jg >> 4][0];
    unsigned* sigA = &g_sig[bgi][0][0];
    unsigned* sigB = &g_sig[bgi][1][0];

    // ---- load W slice (32 j x 1024 k, hi+lo) into padded smem ----
#pragma unroll 8
    for (int it = 0; it < 32; it++) {
        int q = tid + R_THREADS * it;
        int comp = q >> 12, row = (q >> 7) & 31, g = q & 127;
        const __nv_bfloat16* src =
            (comp ? g_wlo : g_whi) + (size_t)(cta_j0 + row) * HID + g * 8;
        *(uint4*)(smc + (comp ? SM_WLO : SM_WHI) + row * 2064 + g * 16) =
            *(const uint4*)src;
    }
    __syncthreads();

    uint32_t b_base[2][2];
#pragma unroll
    for (int comp = 0; comp < 2; comp++)
#pragma unroll
        for (int half = 0; half < 2; half++)
            b_base[comp][half] = smb + (comp ? SM_WLO : SM_WHI)
                + (half * 16 + (lane >> 4) * 8 + (lane & 7)) * 2064
                + ((lane >> 3) & 1) * 16;

    const int koffw = w * 128;

    // ---- hoist all W fragments into registers (resident for 512 steps) ----
    uint32_t wf[2][4][2][2][4];    // [chunk][ks][comp][half][reg]
#pragma unroll
    for (int c = 0; c < 2; c++)
#pragma unroll
        for (int ks = 0; ks < 4; ks++)
#pragma unroll
            for (int comp = 0; comp < 2; comp++)
#pragma unroll
                for (int half = 0; half < 2; half++)
                    ldsm4(wf[c][ks][comp][half][0], wf[c][ks][comp][half][1],
                          wf[c][ks][comp][half][2], wf[c][ks][comp][half][3],
                          b_base[comp][half] + c * 1024 + koffw + ks * 32);

    // ---- mbarrier init ----
    const uint32_t mbar0 = smb + SM_MBAR;
    const uint32_t mbar1 = smb + SM_MBAR + 8;
    if (tid == 0) {
        asm volatile("mbarrier.init.shared.b64 [%0], %1;"
                     :: "r"(mbar0), "r"(1u) : "memory");
        asm volatile("mbarrier.init.shared.b64 [%0], %1;"
                     :: "r"(mbar1), "r"(1u) : "memory");
        asm volatile("fence.proxy.async;" ::: "memory");
    }
    __syncthreads();

    // ---- A-fragment swizzled address components ----
    const int arow = lane & 15;          // m row
    const int ahi  = lane >> 4;          // k8 half select
    const int axr  = arow & 7;           // swizzle xor
    uint32_t a_comp[2];
#pragma unroll
    for (int comp = 0; comp < 2; comp++)
        a_comp[comp] = smb + SM_HBUF + comp * IMG_CMP + arow * 128;

    const int o0 = tid * 2;
    const int bl = o0 >> 5, jl = o0 & 31;
    // producer store swizzle (col = cta_j0 + jl, even), chunk-major layout
    const int pcol = cta_j0 + jl;
    const int pc   = pcol & 511;
    const uint32_t pbase = (uint32_t)bgi * IMG_BG
        + (uint32_t)(pcol >> 9) * IMG_CHK
        + (uint32_t)(pc >> 6) * 2048u
        + (uint32_t)bl * 128u
        + (uint32_t)((((pc >> 3) & 7) ^ (bl & 7)) << 4)
        + (uint32_t)((pc & 7) * 2);

    for (int t = 0; t < SEQ; t++) {
        const unsigned phase = (unsigned)(t & 1);
        const unsigned char* img = g_himg + (t & 1) * IMG_PAR + bgi * IMG_BG;

        // orchestrators: parallel per-half detection + 32KB bulk each
        if (tid == 0) {
            if (t) {
                const unsigned need = 16u * (unsigned)t;
                unsigned v;
                do {
                    asm volatile("ld.acquire.gpu.global.u32 %0, [%1];"
                                 : "=r"(v) : "l"(sigA));
                } while (v < need);
            }
            asm volatile("fence.proxy.async;" ::: "memory");
            asm volatile("mbarrier.arrive.expect_tx.shared.b64 _, [%0], %1;"
                         :: "r"(mbar0), "r"(IMG_CHK) : "memory");
            asm volatile(
                "cp.async.bulk.shared::cluster.global.mbarrier::complete_tx::bytes"
                " [%0], [%1], %2, [%3];"
                :: "r"(smb + SM_HBUF), "l"(img), "r"(IMG_CHK), "r"(mbar0)
                : "memory");
        }
        if (tid == 32) {
            if (t) {
                const unsigned need = 16u * (unsigned)t;
                unsigned v;
                do {
                    asm volatile("ld.acquire.gpu.global.u32 %0, [%1];"
                                 : "=r"(v) : "l"(sigB));
                } while (v < need);
            }
            asm volatile("fence.proxy.async;" ::: "memory");
            asm volatile("mbarrier.arrive.expect_tx.shared.b64 _, [%0], %1;"
                         :: "r"(mbar1), "r"(IMG_CHK) : "memory");
            asm volatile(
                "cp.async.bulk.shared::cluster.global.mbarrier::complete_tx::bytes"
                " [%0], [%1], %2, [%3];"
                :: "r"(smb + SM_HBUF + IMG_CHK), "l"(img + IMG_CHK),
                   "r"(IMG_CHK), "r"(mbar1)
                : "memory");
        }

        float2 xp = __ldg((const float2*)
            (g_xp + ((size_t)(cta_b0 + bl) * SEQ + t) * HID + cta_j0 + jl));

        float D1[4][4], D2[4][4];
#pragma unroll
        for (int i = 0; i < 4; i++)
#pragma unroll
            for (int j = 0; j < 4; j++) { D1[i][j] = 0.f; D2[i][j] = 0.f; }

#pragma unroll
        for (int c = 0; c < 2; c++) {
            mbar_wait(c ? mbar1 : mbar0, phase);
            const uint32_t cofs = (uint32_t)c * IMG_CHK + (uint32_t)w * 2048u;
#pragma unroll
            for (int ks = 0; ks < 4; ks++) {
                const uint32_t gsw = (uint32_t)(((ks * 2 + ahi) ^ axr) << 4);
                uint32_t ah[4], al[4];
                ldsm4(ah[0], ah[1], ah[2], ah[3], a_comp[0] + cofs + gsw);
                ldsm4(al[0], al[1], al[2], al[3], a_comp[1] + cofs + gsw);
#pragma unroll
                for (int tt = 0; tt < 4; tt++) {
                    int h2 = tt >> 1, p = (tt & 1) * 2;
                    mma16816(D1[tt], ah[0], ah[1], ah[2], ah[3],
                             wf[c][ks][0][h2][p], wf[c][ks][0][h2][p + 1]);
                }
#pragma unroll
                for (int tt = 0; tt < 4; tt++) {
                    int h2 = tt >> 1, p = (tt & 1) * 2;
                    mma16816(D2[tt], al[0], al[1], al[2], al[3],
                             wf[c][ks][0][h2][p], wf[c][ks][0][h2][p + 1]);
                }
#pragma unroll
                for (int tt = 0; tt < 4; tt++) {
                    int h2 = tt >> 1, p = (tt & 1) * 2;
                    mma16816(D2[tt], ah[0], ah[1], ah[2], ah[3],
                             wf[c][ks][1][h2][p], wf[c][ks][1][h2][p + 1]);
                }
            }
        }

        // ---- cross-warp k reduction via smem ----
#pragma unroll
        for (int tt = 0; tt < 4; tt++)
#pragma unroll
            for (int r = 0; r < 4; r++) {
                int b = (lane >> 2) + ((r >= 2) ? 8 : 0);
                int j = tt * 8 + 2 * (lane & 3) + (r & 1);
                redf[w * RED_ROW + b * 33 + j] = D1[tt][r] + D2[tt][r];
            }
        __syncthreads();

        float v0 = 0.f, v1 = 0.f;
#pragma unroll
        for (int ww = 0; ww < 8; ww++) {
            v0 += redf[ww * RED_ROW + bl * 33 + jl];
            v1 += redf[ww * RED_ROW + bl * 33 + jl + 1];
        }
        v0 = tanhf(v0 + xp.x);
        v1 = tanhf(v1 + xp.y);

        __nv_bfloat16 h0, l0, h1, l1;
        split_bf16(v0, h0, l0);
        split_bf16(v1, h1, l1);
        unsigned char* hb = g_himg + ((t + 1) & 1) * IMG_PAR + pbase;
        __nv_bfloat162 ph; ph.x = h0; ph.y = h1;
        __nv_bfloat162 pl; pl.x = l0; pl.y = l1;
        *(__nv_bfloat162*)(hb)           = ph;
        *(__nv_bfloat162*)(hb + IMG_CMP) = pl;

        __syncthreads();
        if (tid == 0)
            asm volatile("red.release.gpu.global.add.u32 [%0], %1;"
                         :: "l"(my_sig_out), "r"(1u));
    }
}

// ---------------- output projection ------------------------------------------
__global__ __launch_bounds__(256) void k_out(
    const float* __restrict__ Who, const float* __restrict__ bho,
    float* __restrict__ out)
{
    const int lane = threadIdx.x & 31;
    const int gw   = blockIdx.x * 8 + (threadIdx.x >> 5);
    const int o0   = (gw >> 3) * 2;
    const int b0   = (gw & 7) * 8;

    const float4* W0 = (const float4*)(Who + (size_t)o0 * HID);
    const float4* W1 = (const float4*)(Who + (size_t)(o0 + 1) * HID);
    float4 wr0[8], wr1[8];
#pragma unroll
    for (int i = 0; i < 8; i++) {
        wr0[i] = W0[i * 32 + lane];
        wr1[i] = W1[i * 32 + lane];
    }
    float bias0 = __ldg(&bho[o0]), bias1 = __ldg(&bho[o0 + 1]);

    const int gran = (lane >> 1) & 7;     // granule within row
    const int bofs = (lane & 1) * 8;      // byte offset within granule (8B aligned)

#pragma unroll
    for (int b = 0; b < 8; b++) {
        const int bb = b0 + b;
        const int bg = bb >> 4, r = bb & 15;
        // final h (after step 511) lives in parity 0 of the swizzled image
        const unsigned char* base = g_himg + bg * IMG_BG + r * 128
                                  + ((gran ^ (r & 7)) << 4) + bofs;
        float a0 = 0.f, a1 = 0.f;
#pragma unroll
        for (int i = 0; i < 8; i++) {
            // k0 = lane*4 + i*128 -> chunk = i>>2, slab = (i&3)*2 + (lane>>4)
            const uint32_t off = (uint32_t)(i >> 2) * IMG_CHK
                               + (uint32_t)((i & 3) * 2 + (lane >> 4)) * 2048u;
            uint2 uh = *(const uint2*)(base + off);
            uint2 ul = *(const uint2*)(base + off + IMG_CMP);
            float2 f0 = __bfloat1622float2(*(__nv_bfloat162*)&uh.x);
            float2 f1 = __bfloat1622float2(*(__nv_bfloat162*)&uh.y);
            float2 g0 = __bfloat1622float2(*(__nv_bfloat162*)&ul.x);
            float2 g1 = __bfloat1622float2(*(__nv_bfloat162*)&ul.y);
            float hx = f0.x + g0.x, hy = f0.y + g0.y;
            float hz = f1.x + g1.x, hw = f1.y + g1.y;
            a0 += hx * wr0[i].x + hy * wr0[i].y + hz * wr0[i].z + hw * wr0[i].w;
            a1 += hx * wr1[i].x + hy * wr1[i].y + hz * wr1[i].z + hw * wr1[i].w;
        }
#pragma unroll
        for (int off = 16; off; off >>= 1) {
            a0 += __shfl_xor_sync(0xffffffffu, a0, off);
            a1 += __shfl_xor_sync(0xffffffffu, a1, off);
        }
        if (lane == 0) {
            out[(size_t)bb * OUTDIM + o0]     = a0 + bias0;
            out[(size_t)bb * OUTDIM + o0 + 1] = a1 + bias1;
        }
    }
}

// ---------------- launch ------------------------------------------------------
extern "C" void kernel_launch(void* const* d_in, const int* in_sizes, int n_in,
                              void* d_out, int out_size)
{
    (void)in_sizes; (void)n_in; (void)out_size;
    const float* X   = (const float*)d_in[0];
    const float* Wih = (const float*)d_in[1];
    const float* bih = (const float*)d_in[2];
    const float* Whh = (const float*)d_in[3];
    const float* bhh = (const float*)d_in[4];
    const float* Who = (const float*)d_in[5];
    const float* bho = (const float*)d_in[6];
    float* out = (float*)d_out;

    cudaFuncSetAttribute(k_xproj, cudaFuncAttributeMaxDynamicSharedMemorySize,
                         XS_BYTES);
    cudaFuncSetAttribute(k_recur, cudaFuncAttributeMaxDynamicSharedMemorySize,
                         SM_BYTES);

    k_init<<<512, 256>>>();
    k_prep<<<65536, 256>>>(X, Whh, Wih, bih, bhh);
    dim3 xg(BATCH * SEQ / 128, HID / 64);
    k_xproj<<<xg, 256, XS_BYTES>>>();
    k_recur<<<R_CTAS, R_THREADS, SM_BYTES>>>();
    k_out<<<256, 256>>>(Who, bho, out);
}

// round 13
// speedup vs baseline: 3.2024x; 1.0332x over previous
#include <cuda_runtime.h>
#include <cuda_bf16.h>
#include <cstdint>

#define BATCH  64
#define SEQ    512
#define INDIM  512
#define HID    1024
#define OUTDIM 512

// ---------------- device scratch ---------------------------------------------
__device__ float          g_xp[(size_t)BATCH * SEQ * HID];     // 128 MB x-projection
__device__ __nv_bfloat16  g_xhi[(size_t)BATCH * SEQ * INDIM];  // X split hi
__device__ __nv_bfloat16  g_xlo[(size_t)BATCH * SEQ * INDIM];  // X split lo
__device__ __nv_bfloat16  g_wihhi[(size_t)HID * INDIM];        // W_ih hi
__device__ __nv_bfloat16  g_wihlo[(size_t)HID * INDIM];        // W_ih lo
__device__ float          g_bias[HID];                         // b_ih + b_hh
__device__ __nv_bfloat16  g_whi[(size_t)HID * HID];            // W_hh hi
__device__ __nv_bfloat16  g_wlo[(size_t)HID * HID];            // W_hh lo
__device__ unsigned       g_sig[4][4][32];                     // [bg][quarter] counters

// hidden state: bulk-copy-ready SWIZZLED image, quarter-major
// [par 2][bg 4][quarter 4][comp 2][slab 4][row 16 x 128 B]; within a row,
// 16B granule g stored at ((g ^ (row&7)) << 4) -> ldmatrix conflict-free.
#define IMG_PAR  262144u
#define IMG_BG   65536u
#define IMG_QTR  16384u
#define IMG_CMP  8192u
__device__ __align__(16) unsigned char g_himg[2 * 4 * IMG_BG];

// ---------------- mma / ldmatrix helpers -------------------------------------
__device__ __forceinline__ void ldsm4(uint32_t &r0, uint32_t &r1, uint32_t &r2,
                                      uint32_t &r3, uint32_t addr) {
    asm volatile("ldmatrix.sync.aligned.m8n8.x4.shared.b16 {%0,%1,%2,%3}, [%4];"
                 : "=r"(r0), "=r"(r1), "=r"(r2), "=r"(r3) : "r"(addr));
}
__device__ __forceinline__ void mma16816(float* d, uint32_t a0, uint32_t a1,
                                         uint32_t a2, uint32_t a3,
                                         uint32_t b0, uint32_t b1) {
    asm volatile(
        "mma.sync.aligned.m16n8k16.row.col.f32.bf16.bf16.f32 "
        "{%0,%1,%2,%3},{%4,%5,%6,%7},{%8,%9},{%0,%1,%2,%3};"
        : "+f"(d[0]), "+f"(d[1]), "+f"(d[2]), "+f"(d[3])
        : "r"(a0), "r"(a1), "r"(a2), "r"(a3), "r"(b0), "r"(b1));
}
__device__ __forceinline__ void split_bf16(float v, __nv_bfloat16 &hi, __nv_bfloat16 &lo) {
    hi = __float2bfloat16(v);
    lo = __float2bfloat16(v - __bfloat162float(hi));
}
__device__ __forceinline__ void mbar_wait(uint32_t mbar, unsigned phase) {
    uint32_t done;
    asm volatile(
        "{\n\t.reg .pred p;\n\t"
        "mbarrier.try_wait.parity.acquire.cta.shared::cta.b64 p, [%1], %2;\n\t"
        "selp.b32 %0, 1, 0, p;\n\t}"
        : "=r"(done) : "r"(mbar), "r"(phase) : "memory");
    if (!done) {
        asm volatile(
            "{\n\t.reg .pred P1;\n\t"
            "W%=:\n\t"
            "mbarrier.try_wait.parity.acquire.cta.shared::cta.b64 P1, [%0], %1, 0x989680;\n\t"
            "@P1 bra.uni D%=;\n\t"
            "bra.uni W%=;\n\t"
            "D%=:\n\t}"
            :: "r"(mbar), "r"(phase) : "memory");
    }
}

// ---------------- init: zero hidden image + signals --------------------------
__global__ void k_init() {
    int i = blockIdx.x * blockDim.x + threadIdx.x;    // 131072 threads
    if (i < 512) ((unsigned*)g_sig)[i] = 0u;
    ((uint32_t*)g_himg)[i] = 0u;                      // 131072 u32 = 512 KB
}

// ---------------- prep: split X, W_hh, W_ih; fold biases ---------------------
__global__ void k_prep(const float* __restrict__ X, const float* __restrict__ Whh,
                       const float* __restrict__ Wih, const float* __restrict__ bih,
                       const float* __restrict__ bhh) {
    int i = blockIdx.x * blockDim.x + threadIdx.x;    // 16777216 threads
    {
        __nv_bfloat16 hi, lo;
        split_bf16(X[i], hi, lo);
        g_xhi[i] = hi; g_xlo[i] = lo;
    }
    if (i < HID * HID) {
        __nv_bfloat16 hi, lo;
        split_bf16(Whh[i], hi, lo);
        g_whi[i] = hi; g_wlo[i] = lo;
    }
    if (i < HID * INDIM) {
        __nv_bfloat16 hi, lo;
        split_bf16(Wih[i], hi, lo);
        g_wihhi[i] = hi; g_wihlo[i] = lo;
    }
    if (i < HID) g_bias[i] = bih[i] + bhh[i];
}

// ---------------- x_proj tensor-core GEMM (BM=128, BN=128, BK=64) ------------
#define XROW     144
#define XA_COMP  (128 * XROW)
#define XA_STAGE (2 * XA_COMP)
#define XB_COMP  (128 * XROW)
#define XB_STAGE (2 * XB_COMP)
#define XS_A     0
#define XS_B     (2 * XA_STAGE)
#define XS_BYTES (XS_B + 2 * XB_STAGE)     // 147456

__device__ __forceinline__ void xp_stage(uint32_t smb, int s, int kt,
                                         int m0, int n0, int tid) {
    const int kb = kt * 64;
#pragma unroll
    for (int r = 0; r < 8; r++) {                    // A: 2048 granules
        int q = tid + 256 * r;
        int c = q >> 10, row = (q >> 3) & 127, kg = q & 7;
        const __nv_bfloat16* src =
            (c ? g_xlo : g_xhi) + (size_t)(m0 + row) * INDIM + kb + kg * 8;
        uint32_t dst = smb + XS_A + s * XA_STAGE + c * XA_COMP + row * XROW + kg * 16;
        asm volatile("cp.async.cg.shared.global [%0], [%1], 16;" :: "r"(dst), "l"(src));
    }
#pragma unroll
    for (int r = 0; r < 8; r++) {                    // B: 2048 granules
        int q = tid + 256 * r;
        int c = q >> 10, row = (q >> 3) & 127, kg = q & 7;
        const __nv_bfloat16* src =
            (c ? g_wihlo : g_wihhi) + (size_t)(n0 + row) * INDIM + kb + kg * 8;
        uint32_t dst = smb + XS_B + s * XB_STAGE + c * XB_COMP + row * XROW + kg * 16;
        asm volatile("cp.async.cg.shared.global [%0], [%1], 16;" :: "r"(dst), "l"(src));
    }
}

__global__ __launch_bounds__(256) void k_xproj()
{
    extern __shared__ char smc[];
    const uint32_t smb = (uint32_t)__cvta_generic_to_shared(smc);

    const int tid  = threadIdx.x;
    const int lane = tid & 31;
    const int w    = tid >> 5;
    const int wm   = (w >> 1) * 32;
    const int wn   = (w & 1) * 64;
    const int m0   = blockIdx.x * 128;
    const int n0   = blockIdx.y * 128;

    float D[2][8][4];                      // single accumulator (hh+lh+hl)
#pragma unroll
    for (int i = 0; i < 2; i++)
#pragma unroll
        for (int j = 0; j < 8; j++)
#pragma unroll
            for (int r = 0; r < 4; r++) D[i][j][r] = 0.f;

    const uint32_t aoff = (wm + (lane & 15)) * XROW + (lane >> 4) * 16;
    uint32_t boff[4];
#pragma unroll
    for (int half = 0; half < 4; half++)
        boff[half] = (wn + half * 16 + (lane >> 4) * 8 + (lane & 7)) * XROW
                   + ((lane >> 3) & 1) * 16;

    xp_stage(smb, 0, 0, m0, n0, tid);
    asm volatile("cp.async.commit_group;");

    for (int kt = 0; kt < INDIM / 64; kt++) {
        const int s = kt & 1;
        if (kt + 1 < INDIM / 64) {
            xp_stage(smb, s ^ 1, kt + 1, m0, n0, tid);
            asm volatile("cp.async.commit_group;");
            asm volatile("cp.async.wait_group 1;");
        } else {
            asm volatile("cp.async.wait_group 0;");
        }
        __syncthreads();

        const uint32_t ah_b = smb + XS_A + s * XA_STAGE + aoff;
        const uint32_t al_b = ah_b + XA_COMP;
        const uint32_t bs_b = smb + XS_B + s * XB_STAGE;

#pragma unroll
        for (int ks = 0; ks < 4; ks++) {
            const uint32_t ka = ks * 32;
            uint32_t ah[2][4], al[2][4], bh[4][4], bl[4][4];
            ldsm4(ah[0][0], ah[0][1], ah[0][2], ah[0][3], ah_b + ka);
            ldsm4(ah[1][0], ah[1][1], ah[1][2], ah[1][3], ah_b + 16 * XROW + ka);
            ldsm4(al[0][0], al[0][1], al[0][2], al[0][3], al_b + ka);
            ldsm4(al[1][0], al[1][1], al[1][2], al[1][3], al_b + 16 * XROW + ka);
#pragma unroll
            for (int h = 0; h < 4; h++) {
                ldsm4(bh[h][0], bh[h][1], bh[h][2], bh[h][3], bs_b + boff[h] + ka);
                ldsm4(bl[h][0], bl[h][1], bl[h][2], bl[h][3],
                      bs_b + XB_COMP + boff[h] + ka);
            }
#pragma unroll
            for (int mi = 0; mi < 2; mi++)
#pragma unroll
                for (int o = 0; o < 8; o++) {
                    int h = o >> 1, p = (o & 1) * 2;
                    mma16816(D[mi][o], ah[mi][0], ah[mi][1], ah[mi][2], ah[mi][3],
                             bh[h][p], bh[h][p + 1]);
                    mma16816(D[mi][o], al[mi][0], al[mi][1], al[mi][2], al[mi][3],
                             bh[h][p], bh[h][p + 1]);
                    mma16816(D[mi][o], ah[mi][0], ah[mi][1], ah[mi][2], ah[mi][3],
                             bl[h][p], bl[h][p + 1]);
                }
        }
        __syncthreads();
    }

    const int rbase = lane >> 2;
    const int cbase = 2 * (lane & 3);
#pragma unroll
    for (int mi = 0; mi < 2; mi++)
#pragma unroll
        for (int o = 0; o < 8; o++) {
            int gm = m0 + wm + mi * 16 + rbase;
            int gn = n0 + wn + o * 8 + cbase;
            float2 b2 = *(const float2*)&g_bias[gn];
            float2 v;
            v.x = D[mi][o][0] + b2.x;
            v.y = D[mi][o][1] + b2.y;
            *(float2*)(g_xp + (size_t)gm * HID + gn) = v;
            v.x = D[mi][o][2] + b2.x;
            v.y = D[mi][o][3] + b2.y;
            *(float2*)(g_xp + (size_t)(gm + 8) * HID + gn) = v;
        }
}

// ---------------- recurrence: persistent tensor-core kernel ------------------
// 128 CTAs x 256 threads; 4 independent 32-CTA bg chains. Exchange split into
// 4 QUARTERS (k-256 each, 8 producers each). Warp w owns contiguous k-slice
// [w*128, w*128+128) -> entirely inside quarter w>>1: each warp waits ONLY its
// quarter's mbarrier. Orchestrators: lane 0 of warps 0/2/4/6 poll their own
// quarter counter and issue a 16 KB bulk copy — own quarter == compute quarter.
#define R_CTAS    128
#define R_THREADS 256

#define SM_WHI   0                       // [32][1032] bf16 (row 2064 B)
#define SM_WLO   66048
#define SM_HBUF  132096                  // 64 KB swizzled h image slice
#define SM_RED   197632                  // [8][528] f32
#define RED_ROW  528
#define SM_MBAR  214528                  // 4 mbarriers
#define SM_BYTES 214784

__global__ __launch_bounds__(R_THREADS, 1) void k_recur()
{
    extern __shared__ char smc[];
    const uint32_t smb = (uint32_t)__cvta_generic_to_shared(smc);
    float* redf = (float*)(smc + SM_RED);

    const int tid  = threadIdx.x;
    const int lane = tid & 31;
    const int w    = tid >> 5;
    const int jg   = blockIdx.x & 31;
    const int bgi  = blockIdx.x >> 5;
    const int cta_j0 = jg * 32;
    const int cta_b0 = bgi * 16;

    unsigned* my_sig_out = &g_sig[bgi][jg >> 3][0];

    // ---- load W slice (32 j x 1024 k, hi+lo) into padded smem ----
#pragma unroll 8
    for (int it = 0; it < 32; it++) {
        int q = tid + R_THREADS * it;
        int comp = q >> 12, row = (q >> 7) & 31, g = q & 127;
        const __nv_bfloat16* src =
            (comp ? g_wlo : g_whi) + (size_t)(cta_j0 + row) * HID + g * 8;
        *(uint4*)(smc + (comp ? SM_WLO : SM_WHI) + row * 2064 + g * 16) =
            *(const uint4*)src;
    }
    __syncthreads();

    uint32_t b_base[2][2];
#pragma unroll
    for (int comp = 0; comp < 2; comp++)
#pragma unroll
        for (int half = 0; half < 2; half++)
            b_base[comp][half] = smb + (comp ? SM_WLO : SM_WHI)
                + (half * 16 + (lane >> 4) * 8 + (lane & 7)) * 2064
                + ((lane >> 3) & 1) * 16;

    // ---- hoist W fragments: warp w owns CONTIGUOUS k [w*128, w*128+128) ----
    uint32_t wf[8][2][2][4];    // [ktile][comp][nhalf][reg]
#pragma unroll
    for (int ks = 0; ks < 8; ks++)
#pragma unroll
        for (int comp = 0; comp < 2; comp++)
#pragma unroll
            for (int half = 0; half < 2; half++)
                ldsm4(wf[ks][comp][half][0], wf[ks][comp][half][1],
                      wf[ks][comp][half][2], wf[ks][comp][half][3],
                      b_base[comp][half] + w * 256 + ks * 32);

    // ---- mbarrier init (4) ----
    if (tid == 0) {
#pragma unroll
        for (int q = 0; q < 4; q++)
            asm volatile("mbarrier.init.shared.b64 [%0], %1;"
                         :: "r"(smb + SM_MBAR + q * 8), "r"(1u) : "memory");
        asm volatile("fence.proxy.async;" ::: "memory");
    }
    __syncthreads();

    // ---- A-fragment swizzled base: quarter w>>1, slabs (w&1)*2 + {0,1} ----
    const int arow = lane & 15;
    const int ahi  = lane >> 4;
    const int axr  = arow & 7;
    const uint32_t a_qbase = smb + SM_HBUF + (uint32_t)(w >> 1) * IMG_QTR
                           + (uint32_t)(w & 1) * 2u * 2048u + (uint32_t)arow * 128u;
    const uint32_t my_mbar = smb + SM_MBAR + (uint32_t)(w >> 1) * 8u;

    const int o0 = tid * 2;
    const int bl = o0 >> 5, jl = o0 & 31;
    // producer store address (quarter-major layout)
    const int pcol = cta_j0 + jl;
    const int pc   = pcol & 255;
    const uint32_t pbase = (uint32_t)bgi * IMG_BG
        + (uint32_t)(pcol >> 8) * IMG_QTR
        + (uint32_t)(pc >> 6) * 2048u
        + (uint32_t)bl * 128u
        + (uint32_t)((((pc >> 3) & 7) ^ (bl & 7)) << 4)
        + (uint32_t)((pc & 7) * 2);

    for (int t = 0; t < SEQ; t++) {
        const unsigned phase = (unsigned)(t & 1);
        const unsigned char* img = g_himg + (t & 1) * IMG_PAR + bgi * IMG_BG;

        // orchestrators: lane 0 of warps 0/2/4/6 handle quarter tid>>6
        if ((tid & 63) == 0) {
            const int q = tid >> 6;
            if (t) {
                const unsigned need = 8u * (unsigned)t;
                const unsigned* sp = &g_sig[bgi][q][0];
                unsigned v;
                do {
                    asm volatile("ld.acquire.gpu.global.u32 %0, [%1];"
                                 : "=r"(v) : "l"(sp));
                } while (v < need);
            }
            asm volatile("fence.proxy.async;" ::: "memory");
            const uint32_t mb = smb + SM_MBAR + q * 8;
            asm volatile("mbarrier.arrive.expect_tx.shared.b64 _, [%0], %1;"
                         :: "r"(mb), "r"(IMG_QTR) : "memory");
            asm volatile(
                "cp.async.bulk.shared::cluster.global.mbarrier::complete_tx::bytes"
                " [%0], [%1], %2, [%3];"
                :: "r"(smb + SM_HBUF + q * IMG_QTR), "l"(img + q * IMG_QTR),
                   "r"(IMG_QTR), "r"(mb)
                : "memory");
        }

        float2 xp = __ldg((const float2*)
            (g_xp + ((size_t)(cta_b0 + bl) * SEQ + t) * HID + cta_j0 + jl));

        float D1[4][4], D2[4][4];
#pragma unroll
        for (int i = 0; i < 4; i++)
#pragma unroll
            for (int j = 0; j < 4; j++) { D1[i][j] = 0.f; D2[i][j] = 0.f; }

        // wait only for THIS warp's quarter
        mbar_wait(my_mbar, phase);

#pragma unroll
        for (int ks = 0; ks < 8; ks++) {
            const uint32_t addr = a_qbase + (uint32_t)(ks >> 2) * 2048u
                + (uint32_t)((((ks & 3) * 2 + ahi) ^ axr) << 4);
            uint32_t ah[4], al[4];
            ldsm4(ah[0], ah[1], ah[2], ah[3], addr);
            ldsm4(al[0], al[1], al[2], al[3], addr + IMG_CMP);
#pragma unroll
            for (int tt = 0; tt < 4; tt++) {
                int h2 = tt >> 1, p = (tt & 1) * 2;
                mma16816(D1[tt], ah[0], ah[1], ah[2], ah[3],
                         wf[ks][0][h2][p], wf[ks][0][h2][p + 1]);
            }
#pragma unroll
            for (int tt = 0; tt < 4; tt++) {
                int h2 = tt >> 1, p = (tt & 1) * 2;
                mma16816(D2[tt], al[0], al[1], al[2], al[3],
                         wf[ks][0][h2][p], wf[ks][0][h2][p + 1]);
            }
#pragma unroll
            for (int tt = 0; tt < 4; tt++) {
                int h2 = tt >> 1, p = (tt & 1) * 2;
                mma16816(D2[tt], ah[0], ah[1], ah[2], ah[3],
                         wf[ks][1][h2][p], wf[ks][1][h2][p + 1]);
            }
        }

        // ---- cross-warp k reduction via smem ----
#pragma unroll
        for (int tt = 0; tt < 4; tt++)
#pragma unroll
            for (int r = 0; r < 4; r++) {
                int b = (lane >> 2) + ((r >= 2) ? 8 : 0);
                int j = tt * 8 + 2 * (lane & 3) + (r & 1);
                redf[w * RED_ROW + b * 33 + j] = D1[tt][r] + D2[tt][r];
            }
        __syncthreads();

        float v0 = 0.f, v1 = 0.f;
#pragma unroll
        for (int ww = 0; ww < 8; ww++) {
            v0 += redf[ww * RED_ROW + bl * 33 + jl];
            v1 += redf[ww * RED_ROW + bl * 33 + jl + 1];
        }
        v0 = tanhf(v0 + xp.x);
        v1 = tanhf(v1 + xp.y);

        __nv_bfloat16 h0, l0, h1, l1;
        split_bf16(v0, h0, l0);
        split_bf16(v1, h1, l1);
        unsigned char* hb = g_himg + ((t + 1) & 1) * IMG_PAR + pbase;
        __nv_bfloat162 ph; ph.x = h0; ph.y = h1;
        __nv_bfloat162 pl; pl.x = l0; pl.y = l1;
        *(__nv_bfloat162*)(hb)           = ph;
        *(__nv_bfloat162*)(hb + IMG_CMP) = pl;

        __syncthreads();
        if (tid == 0)
            asm volatile("red.release.gpu.global.add.u32 [%0], %1;"
                         :: "l"(my_sig_out), "r"(1u));
    }
}

// ---------------- output projection ------------------------------------------
__global__ __launch_bounds__(256) void k_out(
    const float* __restrict__ Who, const float* __restrict__ bho,
    float* __restrict__ out)
{
    const int lane = threadIdx.x & 31;
    const int gw   = blockIdx.x * 8 + (threadIdx.x >> 5);
    const int o0   = (gw >> 3) * 2;
    const int b0   = (gw & 7) * 8;

    const float4* W0 = (const float4*)(Who + (size_t)o0 * HID);
    const float4* W1 = (const float4*)(Who + (size_t)(o0 + 1) * HID);
    float4 wr0[8], wr1[8];
#pragma unroll
    for (int i = 0; i < 8; i++) {
        wr0[i] = W0[i * 32 + lane];
        wr1[i] = W1[i * 32 + lane];
    }
    float bias0 = __ldg(&bho[o0]), bias1 = __ldg(&bho[o0 + 1]);

    const int gran = (lane >> 1) & 7;     // granule within row
    const int bofs = (lane & 1) * 8;      // byte offset within granule (8B aligned)

#pragma unroll
    for (int b = 0; b < 8; b++) {
        const int bb = b0 + b;
        const int bg = bb >> 4, r = bb & 15;
        // final h (after step 511) lives in parity 0 of the swizzled image
        const unsigned char* base = g_himg + bg * IMG_BG + r * 128
                                  + ((gran ^ (r & 7)) << 4) + bofs;
        float a0 = 0.f, a1 = 0.f;
#pragma unroll
        for (int i = 0; i < 8; i++) {
            // k0 = lane*4 + i*128 -> quarter = i>>1, slab = (i&1)*2 + (lane>>4)
            const uint32_t off = (uint32_t)(i >> 1) * IMG_QTR
                               + (uint32_t)((i & 1) * 2 + (lane >> 4)) * 2048u;
            uint2 uh = *(const uint2*)(base + off);
            uint2 ul = *(const uint2*)(base + off + IMG_CMP);
            float2 f0 = __bfloat1622float2(*(__nv_bfloat162*)&uh.x);
            float2 f1 = __bfloat1622float2(*(__nv_bfloat162*)&uh.y);
            float2 g0 = __bfloat1622float2(*(__nv_bfloat162*)&ul.x);
            float2 g1 = __bfloat1622float2(*(__nv_bfloat162*)&ul.y);
            float hx = f0.x + g0.x, hy = f0.y + g0.y;
            float hz = f1.x + g1.x, hw = f1.y + g1.y;
            a0 += hx * wr0[i].x + hy * wr0[i].y + hz * wr0[i].z + hw * wr0[i].w;
            a1 += hx * wr1[i].x + hy * wr1[i].y + hz * wr1[i].z + hw * wr1[i].w;
        }
#pragma unroll
        for (int off = 16; off; off >>= 1) {
            a0 += __shfl_xor_sync(0xffffffffu, a0, off);
            a1 += __shfl_xor_sync(0xffffffffu, a1, off);
        }
        if (lane == 0) {
            out[(size_t)bb * OUTDIM + o0]     = a0 + bias0;
            out[(size_t)bb * OUTDIM + o0 + 1] = a1 + bias1;
        }
    }
}

// ---------------- launch ------------------------------------------------------
extern "C" void kernel_launch(void* const* d_in, const int* in_sizes, int n_in,
                              void* d_out, int out_size)
{
    (void)in_sizes; (void)n_in; (void)out_size;
    const float* X   = (const float*)d_in[0];
    const float* Wih = (const float*)d_in[1];
    const float* bih = (const float*)d_in[2];
    const float* Whh = (const float*)d_in[3];
    const float* bhh = (const float*)d_in[4];
    const float* Who = (const float*)d_in[5];
    const float* bho = (const float*)d_in[6];
    float* out = (float*)d_out;

    cudaFuncSetAttribute(k_xproj, cudaFuncAttributeMaxDynamicSharedMemorySize,
                         XS_BYTES);
    cudaFuncSetAttribute(k_recur, cudaFuncAttributeMaxDynamicSharedMemorySize,
                         SM_BYTES);

    k_init<<<512, 256>>>();
    k_prep<<<65536, 256>>>(X, Whh, Wih, bih, bhh);
    dim3 xg(BATCH * SEQ / 128, HID / 128);
    k_xproj<<<xg, 256, XS_BYTES>>>();
    k_recur<<<R_CTAS, R_THREADS, SM_BYTES>>>();
    k_out<<<256, 256>>>(Who, bho, out);
}